// round 2
// baseline (speedup 1.0000x reference)
#include <cuda_runtime.h>
#include <cuda_bf16.h>
#include <cstdint>

// Problem constants (fixed shapes for this problem instance)
#define TT 16384
#define HH 2048
#define FFD 8192
#define EE 8
#define RR 16

#define NSEG 16
#define FSEG (FFD / NSEG)   // 512
#define FCC  256            // f-chunk staged in smem
#define PAD  20             // smem row stride (floats): 16B-aligned, conflict-mitigating

typedef unsigned long long u64;

// ---------------- scratch (device globals; no allocation allowed) --------------
__device__ float g_z1[TT * RR];                 // 1 MB
__device__ float g_z2p[NSEG * TT * RR];         // 16 MB  (per-FF-segment partials)
__device__ float g_z2[TT * RR];                 // 1 MB
__device__ long long g_off[EE + 1];

// ---------------- helpers ------------------------------------------------------
__device__ __forceinline__ u64 ffma2(u64 a, u64 b, u64 c) {
    u64 d;
    asm("fma.rn.f32x2 %0, %1, %2, %3;" : "=l"(d) : "l"(a), "l"(b), "l"(c));
    return d;
}
__device__ __forceinline__ u64 pack2(float x, float y) {
    u64 r;
    asm("mov.b64 %0, {%1, %2};" : "=l"(r) : "f"(x), "f"(y));
    return r;
}
__device__ __forceinline__ float2 unpack2(u64 v) {
    float2 r;
    asm("mov.b64 {%0, %1}, %2;" : "=f"(r.x), "=f"(r.y) : "l"(v));
    return r;
}

// exact-gelu via Abramowitz&Stegun 7.1.26 erf (|abs err| <= 1.5e-7)
__device__ __forceinline__ float gelu_f(float x) {
    float ax = fabsf(x) * 0.7071067811865475f;
    float t  = __fdividef(1.0f, fmaf(0.3275911f, ax, 1.0f));
    float p  = fmaf(t, 1.061405429f, -1.453152027f);
    p = fmaf(p, t, 1.421413741f);
    p = fmaf(p, t, -0.284496736f);
    p = fmaf(p, t, 0.254829592f);
    p *= t;
    float ex = __expf(-ax * ax);
    float er = fmaf(-p, ex, 1.0f);      // erf(|x|/sqrt2)
    er = copysignf(er, x);
    return 0.5f * x * (1.0f + er);
}

__device__ __forceinline__ int expert_of(int t) {
    int e = 0;
#pragma unroll
    for (int i = 1; i <= EE; i++)
        if ((long long)t >= g_off[i]) e = i;
    return e;   // == EE means "no expert" (zero output)
}

// ---------------- k0: expert cumsum bounds (dtype-agnostic: int32 or int64) ----
__global__ void k0_bounds(const void* __restrict__ tpe_raw) {
    if (threadIdx.x == 0) {
        const int* p32 = (const int*)tpe_raw;
        long long s32 = 0;
#pragma unroll
        for (int i = 0; i < EE; i++) s32 += (long long)p32[i];
        long long a = 0;
        g_off[0] = 0;
        if (s32 == (long long)TT) {
            // JAX default (x64 disabled): int64 request silently becomes int32
#pragma unroll
            for (int i = 0; i < EE; i++) { a += (long long)p32[i]; g_off[i + 1] = a; }
        } else {
            // genuine int64 buffer (safe to read 64 bytes only in this case)
            const long long* p64 = (const long long*)tpe_raw;
#pragma unroll
            for (int i = 0; i < EE; i++) { a += p64[i]; g_off[i + 1] = a; }
        }
    }
}

// ---------------- k1: z1[t,r] = sum_h x[t,h] * w1A[e*R+r, h] ------------------
__global__ __launch_bounds__(256) void k1_z1(const float* __restrict__ x,
                                             const float* __restrict__ w1A) {
    int token = blockIdx.x * 16 + threadIdx.y;
    int r = threadIdx.x;            // 0..15
    int e = expert_of(token);
    float a0 = 0.f, a1 = 0.f, a2 = 0.f, a3 = 0.f;
    if (e < EE) {
        const float4* xp = (const float4*)(x + (size_t)token * HH);
        const float4* ap = (const float4*)(w1A + (size_t)(e * RR + r) * HH);
#pragma unroll 4
        for (int k = 0; k < HH / 4; k++) {
            float4 xv = xp[k];
            float4 av = ap[k];
            a0 = fmaf(xv.x, av.x, a0);
            a1 = fmaf(xv.y, av.y, a1);
            a2 = fmaf(xv.z, av.z, a2);
            a3 = fmaf(xv.w, av.w, a3);
        }
    }
    g_z1[token * RR + r] = (a0 + a1) + (a2 + a3);
}

// ---------------- k2: fused  z2 += gelu(z1 @ B1) @ A2^T  over one FF segment --
__global__ __launch_bounds__(256) void k2_mid(const float* __restrict__ w1B,
                                              const float* __restrict__ w2A) {
    __shared__ float Bs[FCC][PAD];
    __shared__ float As[FCC][PAD];

    int token  = blockIdx.x * 256 + threadIdx.x;
    int seg    = blockIdx.y;
    int fbase0 = seg * FSEG;

    int e       = expert_of(token);
    int e_first = expert_of(blockIdx.x * 256);
    int e_last  = expert_of(blockIdx.x * 256 + 255);
    bool uniform = (e_first == e_last);      // block-uniform predicate

    float z1r[RR];
#pragma unroll
    for (int i = 0; i < 4; i++) {
        float4 v = *(const float4*)&g_z1[token * RR + i * 4];
        z1r[i * 4 + 0] = v.x; z1r[i * 4 + 1] = v.y;
        z1r[i * 4 + 2] = v.z; z1r[i * 4 + 3] = v.w;
    }

    float acc[RR];
#pragma unroll
    for (int i = 0; i < RR; i++) acc[i] = 0.f;

    if (uniform && e_first < EE) {
        // fast path: stage B1/A2 chunk (transposed, f-major rows) in smem
        u64 zp[8];
#pragma unroll
        for (int p = 0; p < 8; p++) zp[p] = pack2(z1r[2 * p], z1r[2 * p + 1]);
        u64 ap8[8];
#pragma unroll
        for (int p = 0; p < 8; p++) ap8[p] = 0ull;   // bits(0,0) == (0.f,0.f)

        for (int c = 0; c < FSEG / FCC; c++) {
            int fb = fbase0 + c * FCC;
            __syncthreads();
            {
                int f = threadIdx.x;                 // 0..255, coalesced in f
#pragma unroll
                for (int r = 0; r < RR; r++) {
                    size_t row = (size_t)(e_first * RR + r);
                    Bs[f][r] = w1B[row * FFD + fb + f];
                    As[f][r] = w2A[row * FFD + fb + f];
                }
            }
            __syncthreads();

#pragma unroll 2
            for (int f = 0; f < FCC; f++) {
                const ulonglong2* bq = (const ulonglong2*)&Bs[f][0];
                ulonglong2 q0 = bq[0], q1 = bq[1];
                u64 sA = ffma2(zp[0], q0.x, 0ull);
                sA = ffma2(zp[1], q0.y, sA);
                sA = ffma2(zp[2], q1.x, sA);
                sA = ffma2(zp[3], q1.y, sA);
                ulonglong2 q2 = bq[2], q3 = bq[3];
                u64 sB = ffma2(zp[4], q2.x, 0ull);
                sB = ffma2(zp[5], q2.y, sB);
                sB = ffma2(zp[6], q3.x, sB);
                sB = ffma2(zp[7], q3.y, sB);
                float2 va = unpack2(sA);
                float2 vb = unpack2(sB);
                float h = gelu_f((va.x + va.y) + (vb.x + vb.y));
                u64 h2 = pack2(h, h);
                const ulonglong2* aq = (const ulonglong2*)&As[f][0];
                ulonglong2 p0 = aq[0], p1 = aq[1], p2 = aq[2], p3 = aq[3];
                ap8[0] = ffma2(h2, p0.x, ap8[0]);
                ap8[1] = ffma2(h2, p0.y, ap8[1]);
                ap8[2] = ffma2(h2, p1.x, ap8[2]);
                ap8[3] = ffma2(h2, p1.y, ap8[3]);
                ap8[4] = ffma2(h2, p2.x, ap8[4]);
                ap8[5] = ffma2(h2, p2.y, ap8[5]);
                ap8[6] = ffma2(h2, p3.x, ap8[6]);
                ap8[7] = ffma2(h2, p3.y, ap8[7]);
            }
        }
#pragma unroll
        for (int p = 0; p < 8; p++) {
            float2 v = unpack2(ap8[p]);
            acc[2 * p] = v.x;
            acc[2 * p + 1] = v.y;
        }
    } else {
        // general (expert-boundary-crossing) slow path: direct global reads
        if (e < EE) {
            for (int f = fbase0; f < fbase0 + FSEG; f++) {
                float hv = 0.f;
#pragma unroll
                for (int r = 0; r < RR; r++)
                    hv = fmaf(z1r[r], w1B[(size_t)(e * RR + r) * FFD + f], hv);
                float h = gelu_f(hv);
#pragma unroll
                for (int r = 0; r < RR; r++)
                    acc[r] = fmaf(h, w2A[(size_t)(e * RR + r) * FFD + f], acc[r]);
            }
        }
    }

#pragma unroll
    for (int i = 0; i < 4; i++) {
        float4 v = make_float4(acc[i * 4 + 0], acc[i * 4 + 1],
                               acc[i * 4 + 2], acc[i * 4 + 3]);
        *(float4*)&g_z2p[((size_t)seg * TT + token) * RR + i * 4] = v;
    }
}

// ---------------- k2r: reduce FF-segment partials ------------------------------
__global__ __launch_bounds__(256) void k2_reduce() {
    int i = blockIdx.x * 256 + threadIdx.x;      // over T*R/4 float4s
    float4 s = make_float4(0.f, 0.f, 0.f, 0.f);
#pragma unroll
    for (int seg = 0; seg < NSEG; seg++) {
        float4 v = *(const float4*)&g_z2p[(size_t)seg * TT * RR + (size_t)i * 4];
        s.x += v.x; s.y += v.y; s.z += v.z; s.w += v.w;
    }
    *(float4*)&g_z2[(size_t)i * 4] = s;
}

// ---------------- k3: out[t,:] = z2[t,:] @ B2_e --------------------------------
__global__ __launch_bounds__(256) void k3_out(const float* __restrict__ w2B,
                                              float* __restrict__ out) {
    int tok0 = blockIdx.x * 32;
    int hcol = blockIdx.y * 256 + threadIdx.x;
    __shared__ float zs[32 * RR];
    __shared__ int se[32];
    for (int i = threadIdx.x; i < 32 * RR; i += 256) zs[i] = g_z2[tok0 * RR + i];
    if (threadIdx.x < 32) se[threadIdx.x] = expert_of(tok0 + threadIdx.x);
    __syncthreads();

    int ecur = -1;
    float b[RR];
#pragma unroll 1
    for (int t = 0; t < 32; t++) {
        int e = se[t];                            // warp-uniform
        if (e != ecur) {
            ecur = e;
            int ee = (e < EE) ? e : 0;            // e==EE: z2 row is 0 -> out 0
#pragma unroll
            for (int r = 0; r < RR; r++)
                b[r] = w2B[(size_t)(ee * RR + r) * HH + hcol];
        }
        const float4* zp = (const float4*)&zs[t * RR];
        float4 z0 = zp[0], z1 = zp[1], z2v = zp[2], z3 = zp[3];
        float a0 = z0.x * b[0], a1 = z0.y * b[1], a2 = z0.z * b[2], a3 = z0.w * b[3];
        a0 = fmaf(z1.x, b[4], a0);  a1 = fmaf(z1.y, b[5], a1);
        a2 = fmaf(z1.z, b[6], a2);  a3 = fmaf(z1.w, b[7], a3);
        a0 = fmaf(z2v.x, b[8], a0); a1 = fmaf(z2v.y, b[9], a1);
        a2 = fmaf(z2v.z, b[10], a2); a3 = fmaf(z2v.w, b[11], a3);
        a0 = fmaf(z3.x, b[12], a0); a1 = fmaf(z3.y, b[13], a1);
        a2 = fmaf(z3.z, b[14], a2); a3 = fmaf(z3.w, b[15], a3);
        out[(size_t)(tok0 + t) * HH + hcol] = (a0 + a1) + (a2 + a3);
    }
}

// ---------------- launch --------------------------------------------------------
extern "C" void kernel_launch(void* const* d_in, const int* in_sizes, int n_in,
                              void* d_out, int out_size) {
    const float* x   = (const float*)d_in[0];
    const void*  tpe = (const void*)d_in[1];
    const float* w1A = (const float*)d_in[2];
    const float* w1B = (const float*)d_in[3];
    const float* w2A = (const float*)d_in[4];
    const float* w2B = (const float*)d_in[5];
    float* out = (float*)d_out;

    k0_bounds<<<1, 32>>>(tpe);

    dim3 b1(16, 16);
    k1_z1<<<TT / 16, b1>>>(x, w1A);

    dim3 g2(TT / 256, NSEG);
    k2_mid<<<g2, 256>>>(w1B, w2A);

    k2_reduce<<<(TT * RR / 4) / 256, 256>>>();

    dim3 g3(TT / 32, HH / 256);
    k3_out<<<g3, 256>>>(w2B, out);
}

// round 4
// speedup vs baseline: 2.0164x; 2.0164x over previous
#include <cuda_runtime.h>
#include <cuda_bf16.h>
#include <cstdint>

#define TT 16384
#define HH 2048
#define FFD 8192
#define EE 8
#define RR 16

#define NSEG 16
#define FSEG (FFD / NSEG)   // 512
#define FCC  256            // f-chunk staged in smem
#define PAD  20             // smem row stride (floats)

#define K1_TOK 128
#define K1_KC  64           // H columns staged per chunk
#define K1_PADX 4           // xs pad: keeps 16B alignment (stride 68 floats = 272B)

typedef unsigned long long u64;

// ---------------- scratch ------------------------------------------------------
__device__ float g_z1[TT * RR];                 // 1 MB
__device__ float g_z2p[NSEG * TT * RR];         // 16 MB
__device__ float g_z2[TT * RR];                 // 1 MB
__device__ long long g_off[EE + 1];

// ---------------- helpers ------------------------------------------------------
__device__ __forceinline__ u64 ffma2(u64 a, u64 b, u64 c) {
    u64 d;
    asm("fma.rn.f32x2 %0, %1, %2, %3;" : "=l"(d) : "l"(a), "l"(b), "l"(c));
    return d;
}
__device__ __forceinline__ u64 pack2(float x, float y) {
    u64 r;
    asm("mov.b64 %0, {%1, %2};" : "=l"(r) : "f"(x), "f"(y));
    return r;
}
__device__ __forceinline__ float2 unpack2(u64 v) {
    float2 r;
    asm("mov.b64 {%0, %1}, %2;" : "=f"(r.x), "=f"(r.y) : "l"(v));
    return r;
}

__device__ __forceinline__ float gelu_f(float x) {
    float ax = fabsf(x) * 0.7071067811865475f;
    float t  = __fdividef(1.0f, fmaf(0.3275911f, ax, 1.0f));
    float p  = fmaf(t, 1.061405429f, -1.453152027f);
    p = fmaf(p, t, 1.421413741f);
    p = fmaf(p, t, -0.284496736f);
    p = fmaf(p, t, 0.254829592f);
    p *= t;
    float ex = __expf(-ax * ax);
    float er = fmaf(-p, ex, 1.0f);
    er = copysignf(er, x);
    return 0.5f * x * (1.0f + er);
}

__device__ __forceinline__ int expert_of(int t) {
    int e = 0;
#pragma unroll
    for (int i = 1; i <= EE; i++)
        if ((long long)t >= g_off[i]) e = i;
    return e;
}

// ---------------- k0: bounds (dtype-agnostic int32/int64) ----------------------
__global__ void k0_bounds(const void* __restrict__ tpe_raw) {
    if (threadIdx.x == 0) {
        const int* p32 = (const int*)tpe_raw;
        long long s32 = 0;
#pragma unroll
        for (int i = 0; i < EE; i++) s32 += (long long)p32[i];
        long long a = 0;
        g_off[0] = 0;
        if (s32 == (long long)TT) {
#pragma unroll
            for (int i = 0; i < EE; i++) { a += (long long)p32[i]; g_off[i + 1] = a; }
        } else {
            const long long* p64 = (const long long*)tpe_raw;
#pragma unroll
            for (int i = 0; i < EE; i++) { a += p64[i]; g_off[i + 1] = a; }
        }
    }
}

// ---------------- k1: z1 = x @ A1^T (smem-tiled, reg-prefetch pipeline) --------
// block: 256 threads = 128 tokens x 2 K-halves. grid: TT/128 = 128 blocks.
__global__ __launch_bounds__(256) void k1_z1(const float* __restrict__ x,
                                             const float* __restrict__ w1A) {
    __shared__ float xs[K1_TOK][K1_KC + K1_PADX];   // stride 272B: 16B-aligned rows
    __shared__ float as_[RR][K1_KC];
    __shared__ float part[K1_TOK][RR];

    int tid  = threadIdx.x;
    int lt   = tid & 127;
    int half = tid >> 7;
    int tok0 = blockIdx.x * K1_TOK;
    int token = tok0 + lt;

    int e_first = expert_of(tok0);
    int e_last  = expert_of(tok0 + K1_TOK - 1);
    bool uni = (e_first == e_last);

    u64 acc2[RR];
#pragma unroll
    for (int r = 0; r < RR; r++) acc2[r] = 0ull;

    if (uni && e_first < EE) {
        const float* arow = w1A + (size_t)e_first * RR * HH;
        // register prefetch buffers
        float4 px[8], pa;
        // prefetch chunk 0
#pragma unroll
        for (int j = 0; j < 8; j++) {
            int idx = tid + j * 256;
            int row = idx >> 4, c4 = idx & 15;
            px[j] = *(const float4*)&x[(size_t)(tok0 + row) * HH + c4 * 4];
        }
        {
            int row = tid >> 4, c4 = tid & 15;
            pa = *(const float4*)&arow[(size_t)row * HH + c4 * 4];
        }
        int kb = half * (K1_KC / 2);

        for (int c = 0; c < HH / K1_KC; c++) {
            __syncthreads();
            // commit prefetched regs to smem
#pragma unroll
            for (int j = 0; j < 8; j++) {
                int idx = tid + j * 256;
                int row = idx >> 4, c4 = idx & 15;
                *(float4*)&xs[row][c4 * 4] = px[j];
            }
            {
                int row = tid >> 4, c4 = tid & 15;
                *(float4*)&as_[row][c4 * 4] = pa;
            }
            __syncthreads();
            // prefetch next chunk while computing this one
            if (c + 1 < HH / K1_KC) {
                int kc = (c + 1) * K1_KC;
#pragma unroll
                for (int j = 0; j < 8; j++) {
                    int idx = tid + j * 256;
                    int row = idx >> 4, c4 = idx & 15;
                    px[j] = *(const float4*)&x[(size_t)(tok0 + row) * HH + kc + c4 * 4];
                }
                {
                    int row = tid >> 4, c4 = tid & 15;
                    pa = *(const float4*)&arow[(size_t)row * HH + kc + c4 * 4];
                }
            }
            // compute: my half's 32 columns = 16 k-pairs
#pragma unroll 4
            for (int kp = 0; kp < 16; kp++) {
                int k = kb + kp * 2;
                u64 xv = *(const u64*)&xs[lt][k];
#pragma unroll
                for (int r = 0; r < RR; r++) {
                    u64 av = *(const u64*)&as_[r][k];
                    acc2[r] = ffma2(xv, av, acc2[r]);
                }
            }
        }
    } else {
        // slow path (expert boundary inside block) — correct, rarely used
        int e = expert_of(token);
        if (e < EE) {
            const float* xrow = x + (size_t)token * HH;
            const float* arow = w1A + (size_t)e * RR * HH;
            for (int k = half * 1024; k < half * 1024 + 1024; k += 2) {
                u64 xv = pack2(xrow[k], xrow[k + 1]);
#pragma unroll
                for (int r = 0; r < RR; r++) {
                    u64 av = pack2(__ldg(&arow[(size_t)r * HH + k]),
                                   __ldg(&arow[(size_t)r * HH + k + 1]));
                    acc2[r] = ffma2(xv, av, acc2[r]);
                }
            }
        }
    }

    // combine halves and write z1; also zero g_z2 rows for this block
    __syncthreads();
    if (half == 1) {
#pragma unroll
        for (int r = 0; r < RR; r++) {
            float2 v = unpack2(acc2[r]);
            part[lt][r] = v.x + v.y;
        }
    }
    __syncthreads();
    if (half == 0) {
#pragma unroll
        for (int i = 0; i < 4; i++) {
            float4 o;
            float2 v0 = unpack2(acc2[i * 4 + 0]);
            float2 v1 = unpack2(acc2[i * 4 + 1]);
            float2 v2 = unpack2(acc2[i * 4 + 2]);
            float2 v3 = unpack2(acc2[i * 4 + 3]);
            o.x = v0.x + v0.y + part[lt][i * 4 + 0];
            o.y = v1.x + v1.y + part[lt][i * 4 + 1];
            o.z = v2.x + v2.y + part[lt][i * 4 + 2];
            o.w = v3.x + v3.y + part[lt][i * 4 + 3];
            *(float4*)&g_z1[token * RR + i * 4] = o;
        }
    }
    // zero g_z2 region for these 128 tokens (128*16 floats = 512 float4)
    {
        float4 z = make_float4(0.f, 0.f, 0.f, 0.f);
#pragma unroll
        for (int j = 0; j < 2; j++) {
            int idx = tid + j * 256;          // 0..511
            *(float4*)&g_z2[(size_t)tok0 * RR + (size_t)idx * 4] = z;
        }
    }
}

// ---------------- k2: fused gelu(z1@B1)@A2^T — 2 tokens/thread -----------------
__global__ __launch_bounds__(256) void k2_mid(const float* __restrict__ w1B,
                                              const float* __restrict__ w2A) {
    __shared__ float Bs[FCC][PAD];
    __shared__ float As[FCC][PAD];

    int tid   = threadIdx.x;
    int tbase = blockIdx.x * 512;
    int t0 = tbase + tid;
    int t1 = t0 + 256;
    int seg = blockIdx.y;
    int fbase0 = seg * FSEG;

    int e_first = expert_of(tbase);
    int e_last  = expert_of(tbase + 511);
    bool uni = (e_first == e_last);

    u64 zp0[8], zp1[8], a0[8], a1[8];
#pragma unroll
    for (int p = 0; p < 8; p++) { a0[p] = 0ull; a1[p] = 0ull; }
    {
        const ulonglong2* z0q = (const ulonglong2*)&g_z1[t0 * RR];
        const ulonglong2* z1q = (const ulonglong2*)&g_z1[t1 * RR];
#pragma unroll
        for (int q = 0; q < 4; q++) {
            ulonglong2 v0 = z0q[q], v1 = z1q[q];
            zp0[q * 2] = v0.x; zp0[q * 2 + 1] = v0.y;
            zp1[q * 2] = v1.x; zp1[q * 2 + 1] = v1.y;
        }
    }

    if (uni && e_first < EE) {
        for (int c = 0; c < FSEG / FCC; c++) {
            int fb = fbase0 + c * FCC;
            __syncthreads();
            {
                int f = tid;
#pragma unroll
                for (int r = 0; r < RR; r++) {
                    size_t row = (size_t)(e_first * RR + r);
                    Bs[f][r] = w1B[row * FFD + fb + f];
                    As[f][r] = w2A[row * FFD + fb + f];
                }
            }
            __syncthreads();

#pragma unroll 2
            for (int f = 0; f < FCC; f++) {
                const ulonglong2* bq = (const ulonglong2*)&Bs[f][0];
                ulonglong2 q0 = bq[0], q1 = bq[1], q2 = bq[2], q3 = bq[3];
                // token 0
                u64 sA = ffma2(zp0[0], q0.x, 0ull);
                sA = ffma2(zp0[1], q0.y, sA);
                sA = ffma2(zp0[2], q1.x, sA);
                sA = ffma2(zp0[3], q1.y, sA);
                u64 sB = ffma2(zp0[4], q2.x, 0ull);
                sB = ffma2(zp0[5], q2.y, sB);
                sB = ffma2(zp0[6], q3.x, sB);
                sB = ffma2(zp0[7], q3.y, sB);
                // token 1
                u64 tA = ffma2(zp1[0], q0.x, 0ull);
                tA = ffma2(zp1[1], q0.y, tA);
                tA = ffma2(zp1[2], q1.x, tA);
                tA = ffma2(zp1[3], q1.y, tA);
                u64 tB = ffma2(zp1[4], q2.x, 0ull);
                tB = ffma2(zp1[5], q2.y, tB);
                tB = ffma2(zp1[6], q3.x, tB);
                tB = ffma2(zp1[7], q3.y, tB);
                float2 va = unpack2(sA), vb = unpack2(sB);
                float2 wa = unpack2(tA), wb = unpack2(tB);
                float h0 = gelu_f((va.x + va.y) + (vb.x + vb.y));
                float h1 = gelu_f((wa.x + wa.y) + (wb.x + wb.y));
                u64 h02 = pack2(h0, h0);
                u64 h12 = pack2(h1, h1);
                const ulonglong2* aq = (const ulonglong2*)&As[f][0];
                ulonglong2 p0 = aq[0], p1 = aq[1], p2 = aq[2], p3 = aq[3];
                a0[0] = ffma2(h02, p0.x, a0[0]);
                a0[1] = ffma2(h02, p0.y, a0[1]);
                a0[2] = ffma2(h02, p1.x, a0[2]);
                a0[3] = ffma2(h02, p1.y, a0[3]);
                a0[4] = ffma2(h02, p2.x, a0[4]);
                a0[5] = ffma2(h02, p2.y, a0[5]);
                a0[6] = ffma2(h02, p3.x, a0[6]);
                a0[7] = ffma2(h02, p3.y, a0[7]);
                a1[0] = ffma2(h12, p0.x, a1[0]);
                a1[1] = ffma2(h12, p0.y, a1[1]);
                a1[2] = ffma2(h12, p1.x, a1[2]);
                a1[3] = ffma2(h12, p1.y, a1[3]);
                a1[4] = ffma2(h12, p2.x, a1[4]);
                a1[5] = ffma2(h12, p2.y, a1[5]);
                a1[6] = ffma2(h12, p3.x, a1[6]);
                a1[7] = ffma2(h12, p3.y, a1[7]);
            }
        }
    } else {
        // slow path
        int ea = expert_of(t0), eb = expert_of(t1);
        float z0r[RR], z1r[RR], acc0[RR], acc1[RR];
#pragma unroll
        for (int r = 0; r < RR; r++) {
            float2 v0 = unpack2(zp0[r / 2]);
            z0r[r] = (r & 1) ? v0.y : v0.x;
            float2 v1 = unpack2(zp1[r / 2]);
            z1r[r] = (r & 1) ? v1.y : v1.x;
            acc0[r] = 0.f; acc1[r] = 0.f;
        }
        for (int f = fbase0; f < fbase0 + FSEG; f++) {
            if (ea < EE) {
                float hv = 0.f;
#pragma unroll
                for (int r = 0; r < RR; r++)
                    hv = fmaf(z0r[r], w1B[(size_t)(ea * RR + r) * FFD + f], hv);
                float h = gelu_f(hv);
#pragma unroll
                for (int r = 0; r < RR; r++)
                    acc0[r] = fmaf(h, w2A[(size_t)(ea * RR + r) * FFD + f], acc0[r]);
            }
            if (eb < EE) {
                float hv = 0.f;
#pragma unroll
                for (int r = 0; r < RR; r++)
                    hv = fmaf(z1r[r], w1B[(size_t)(eb * RR + r) * FFD + f], hv);
                float h = gelu_f(hv);
#pragma unroll
                for (int r = 0; r < RR; r++)
                    acc1[r] = fmaf(h, w2A[(size_t)(eb * RR + r) * FFD + f], acc1[r]);
            }
        }
#pragma unroll
        for (int p = 0; p < 8; p++) {
            a0[p] = pack2(acc0[2 * p], acc0[2 * p + 1]);
            a1[p] = pack2(acc1[2 * p], acc1[2 * p + 1]);
        }
    }

    // write per-segment partials
    {
        ulonglong2* o0 = (ulonglong2*)&g_z2p[((size_t)seg * TT + t0) * RR];
        ulonglong2* o1 = (ulonglong2*)&g_z2p[((size_t)seg * TT + t1) * RR];
#pragma unroll
        for (int q = 0; q < 4; q++) {
            ulonglong2 v0; v0.x = a0[q * 2]; v0.y = a0[q * 2 + 1];
            ulonglong2 v1; v1.x = a1[q * 2]; v1.y = a1[q * 2 + 1];
            o0[q] = v0;
            o1[q] = v1;
        }
    }
}

// ---------------- k2r: reduce segment partials ---------------------------------
__global__ __launch_bounds__(256) void k2_reduce() {
    int i = blockIdx.x * 256 + threadIdx.x;
    float4 s = *(const float4*)&g_z2[(size_t)i * 4];   // zeroed by k1
#pragma unroll
    for (int seg = 0; seg < NSEG; seg++) {
        float4 v = *(const float4*)&g_z2p[(size_t)seg * TT * RR + (size_t)i * 4];
        s.x += v.x; s.y += v.y; s.z += v.z; s.w += v.w;
    }
    *(float4*)&g_z2[(size_t)i * 4] = s;
}

// ---------------- k3: out = z2 @ B2 (float4 cols, f32x2 accum) -----------------
__global__ __launch_bounds__(256) void k3_out(const float* __restrict__ w2B,
                                              float* __restrict__ out) {
    int tok0 = blockIdx.x * 32;
    int c4   = blockIdx.y * 256 + threadIdx.x;      // float4 column 0..HH/4-1
    __shared__ float zs[32 * RR];
    __shared__ int se[32];
    for (int i = threadIdx.x; i < 32 * RR; i += 256) zs[i] = g_z2[tok0 * RR + i];
    if (threadIdx.x < 32) se[threadIdx.x] = expert_of(tok0 + threadIdx.x);
    __syncthreads();

    int ecur = -1;
    u64 bp[RR * 2];                                  // 16 rows x (xy, zw) pairs
#pragma unroll 1
    for (int t = 0; t < 32; t++) {
        int e = se[t];
        if (e != ecur) {
            ecur = e;
            int ee = (e < EE) ? e : 0;
#pragma unroll
            for (int r = 0; r < RR; r++) {
                float4 b = *(const float4*)&w2B[(size_t)(ee * RR + r) * HH + c4 * 4];
                bp[r * 2]     = pack2(b.x, b.y);
                bp[r * 2 + 1] = pack2(b.z, b.w);
            }
        }
        u64 accA = 0ull, accB = 0ull;
#pragma unroll
        for (int r = 0; r < RR; r++) {
            float zv = zs[t * RR + r];
            u64 z2v = pack2(zv, zv);
            accA = ffma2(z2v, bp[r * 2], accA);
            accB = ffma2(z2v, bp[r * 2 + 1], accB);
        }
        float2 ra = unpack2(accA), rb = unpack2(accB);
        float4 o = make_float4(ra.x, ra.y, rb.x, rb.y);
        *(float4*)&out[(size_t)(tok0 + t) * HH + c4 * 4] = o;
    }
}

// ---------------- launch --------------------------------------------------------
extern "C" void kernel_launch(void* const* d_in, const int* in_sizes, int n_in,
                              void* d_out, int out_size) {
    const float* x   = (const float*)d_in[0];
    const void*  tpe = (const void*)d_in[1];
    const float* w1A = (const float*)d_in[2];
    const float* w1B = (const float*)d_in[3];
    const float* w2A = (const float*)d_in[4];
    const float* w2B = (const float*)d_in[5];
    float* out = (float*)d_out;

    k0_bounds<<<1, 32>>>(tpe);

    k1_z1<<<TT / K1_TOK, 256>>>(x, w1A);

    dim3 g2(TT / 512, NSEG);
    k2_mid<<<g2, 256>>>(w1B, w2A);

    k2_reduce<<<(TT * RR / 4) / 256, 256>>>();

    dim3 g3(TT / 32, HH / 1024);
    k3_out<<<g3, 256>>>(w2B, out);
}

// round 5
// speedup vs baseline: 2.3297x; 1.1554x over previous
#include <cuda_runtime.h>
#include <cuda_bf16.h>
#include <cstdint>

#define TT 16384
#define HH 2048
#define FFD 8192
#define EE 8
#define RR 16

#define NSEG 16
#define FSEG (FFD / NSEG)   // 512
#define FCC  256            // f-chunk staged in smem
#define PAD  20             // smem row stride (floats)

#define K1_TOK 128
#define K1_KC  64           // H columns staged per chunk
#define K1_PADX 4           // xs pad: keeps 16B alignment (stride 68 floats = 272B)

typedef unsigned long long u64;

// ---------------- scratch ------------------------------------------------------
__device__ float g_z1[TT * RR];                 // 1 MB
__device__ float g_z2p[NSEG * TT * RR];         // 16 MB
__device__ float g_z2[TT * RR];                 // 1 MB
__device__ long long g_off[EE + 1];

// ---------------- helpers ------------------------------------------------------
__device__ __forceinline__ u64 ffma2(u64 a, u64 b, u64 c) {
    u64 d;
    asm("fma.rn.f32x2 %0, %1, %2, %3;" : "=l"(d) : "l"(a), "l"(b), "l"(c));
    return d;
}
__device__ __forceinline__ u64 pack2(float x, float y) {
    u64 r;
    asm("mov.b64 %0, {%1, %2};" : "=l"(r) : "f"(x), "f"(y));
    return r;
}
__device__ __forceinline__ float2 unpack2(u64 v) {
    float2 r;
    asm("mov.b64 {%0, %1}, %2;" : "=f"(r.x), "=f"(r.y) : "l"(v));
    return r;
}

// exact gelu (A&S 7.1.26 erf) — used in slow paths and as rare-range fallback
__device__ __forceinline__ float gelu_f(float x) {
    float ax = fabsf(x) * 0.7071067811865475f;
    float t  = __fdividef(1.0f, fmaf(0.3275911f, ax, 1.0f));
    float p  = fmaf(t, 1.061405429f, -1.453152027f);
    p = fmaf(p, t, 1.421413741f);
    p = fmaf(p, t, -0.284496736f);
    p = fmaf(p, t, 0.254829592f);
    p *= t;
    float ex = __expf(-ax * ax);
    float er = fmaf(-p, ex, 1.0f);
    er = copysignf(er, x);
    return 0.5f * x * (1.0f + er);
}

// cheap gelu for |x|<=1: gelu(x) = 0.5x + t*Q(t), t=x^2
// Q(t) = (1/sqrt(2pi)) * (1 - t/6 + t^2/40 - t^3/336 + t^4/3456); abs err <= 9.4e-6
#define GC0 0.3989422804014327f
#define GC1 (-0.06649038006690545f)
#define GC2 0.009973557010035818f
#define GC3 (-0.0011873282154804544f)
#define GC4 0.00011543701400504418f

__device__ __forceinline__ int expert_of(int t) {
    int e = 0;
#pragma unroll
    for (int i = 1; i <= EE; i++)
        if ((long long)t >= g_off[i]) e = i;
    return e;
}

// ---------------- k0: bounds (dtype-agnostic int32/int64) ----------------------
__global__ void k0_bounds(const void* __restrict__ tpe_raw) {
    if (threadIdx.x == 0) {
        const int* p32 = (const int*)tpe_raw;
        long long s32 = 0;
#pragma unroll
        for (int i = 0; i < EE; i++) s32 += (long long)p32[i];
        long long a = 0;
        g_off[0] = 0;
        if (s32 == (long long)TT) {
#pragma unroll
            for (int i = 0; i < EE; i++) { a += (long long)p32[i]; g_off[i + 1] = a; }
        } else {
            const long long* p64 = (const long long*)tpe_raw;
#pragma unroll
            for (int i = 0; i < EE; i++) { a += p64[i]; g_off[i + 1] = a; }
        }
    }
}

// ---------------- k1: z1 = x @ A1^T (smem-tiled, reg-prefetch pipeline) --------
__global__ __launch_bounds__(256) void k1_z1(const float* __restrict__ x,
                                             const float* __restrict__ w1A) {
    __shared__ float xs[K1_TOK][K1_KC + K1_PADX];
    __shared__ float as_[RR][K1_KC];
    __shared__ float part[K1_TOK][RR];

    int tid  = threadIdx.x;
    int lt   = tid & 127;
    int half = tid >> 7;
    int tok0 = blockIdx.x * K1_TOK;
    int token = tok0 + lt;

    int e_first = expert_of(tok0);
    int e_last  = expert_of(tok0 + K1_TOK - 1);
    bool uni = (e_first == e_last);

    u64 acc2[RR];
#pragma unroll
    for (int r = 0; r < RR; r++) acc2[r] = 0ull;

    if (uni && e_first < EE) {
        const float* arow = w1A + (size_t)e_first * RR * HH;
        float4 px[8], pa;
#pragma unroll
        for (int j = 0; j < 8; j++) {
            int idx = tid + j * 256;
            int row = idx >> 4, c4 = idx & 15;
            px[j] = *(const float4*)&x[(size_t)(tok0 + row) * HH + c4 * 4];
        }
        {
            int row = tid >> 4, c4 = tid & 15;
            pa = *(const float4*)&arow[(size_t)row * HH + c4 * 4];
        }
        int kb = half * (K1_KC / 2);

        for (int c = 0; c < HH / K1_KC; c++) {
            __syncthreads();
#pragma unroll
            for (int j = 0; j < 8; j++) {
                int idx = tid + j * 256;
                int row = idx >> 4, c4 = idx & 15;
                *(float4*)&xs[row][c4 * 4] = px[j];
            }
            {
                int row = tid >> 4, c4 = tid & 15;
                *(float4*)&as_[row][c4 * 4] = pa;
            }
            __syncthreads();
            if (c + 1 < HH / K1_KC) {
                int kc = (c + 1) * K1_KC;
#pragma unroll
                for (int j = 0; j < 8; j++) {
                    int idx = tid + j * 256;
                    int row = idx >> 4, c4 = idx & 15;
                    px[j] = *(const float4*)&x[(size_t)(tok0 + row) * HH + kc + c4 * 4];
                }
                {
                    int row = tid >> 4, c4 = tid & 15;
                    pa = *(const float4*)&arow[(size_t)row * HH + kc + c4 * 4];
                }
            }
#pragma unroll 4
            for (int kp = 0; kp < 16; kp++) {
                int k = kb + kp * 2;
                u64 xv = *(const u64*)&xs[lt][k];
#pragma unroll
                for (int r = 0; r < RR; r++) {
                    u64 av = *(const u64*)&as_[r][k];
                    acc2[r] = ffma2(xv, av, acc2[r]);
                }
            }
        }
    } else {
        int e = expert_of(token);
        if (e < EE) {
            const float* xrow = x + (size_t)token * HH;
            const float* arow = w1A + (size_t)e * RR * HH;
            for (int k = half * 1024; k < half * 1024 + 1024; k += 2) {
                u64 xv = pack2(xrow[k], xrow[k + 1]);
#pragma unroll
                for (int r = 0; r < RR; r++) {
                    u64 av = pack2(__ldg(&arow[(size_t)r * HH + k]),
                                   __ldg(&arow[(size_t)r * HH + k + 1]));
                    acc2[r] = ffma2(xv, av, acc2[r]);
                }
            }
        }
    }

    __syncthreads();
    if (half == 1) {
#pragma unroll
        for (int r = 0; r < RR; r++) {
            float2 v = unpack2(acc2[r]);
            part[lt][r] = v.x + v.y;
        }
    }
    __syncthreads();
    if (half == 0) {
#pragma unroll
        for (int i = 0; i < 4; i++) {
            float4 o;
            float2 v0 = unpack2(acc2[i * 4 + 0]);
            float2 v1 = unpack2(acc2[i * 4 + 1]);
            float2 v2 = unpack2(acc2[i * 4 + 2]);
            float2 v3 = unpack2(acc2[i * 4 + 3]);
            o.x = v0.x + v0.y + part[lt][i * 4 + 0];
            o.y = v1.x + v1.y + part[lt][i * 4 + 1];
            o.z = v2.x + v2.y + part[lt][i * 4 + 2];
            o.w = v3.x + v3.y + part[lt][i * 4 + 3];
            *(float4*)&g_z1[token * RR + i * 4] = o;
        }
    }
    {
        float4 z = make_float4(0.f, 0.f, 0.f, 0.f);
#pragma unroll
        for (int j = 0; j < 2; j++) {
            int idx = tid + j * 256;
            *(float4*)&g_z2[(size_t)tok0 * RR + (size_t)idx * 4] = z;
        }
    }
}

// ---------------- k2: fused gelu(z1@B1)@A2^T — 2 tokens/thread, MUFU-free gelu -
__global__ __launch_bounds__(256) void k2_mid(const float* __restrict__ w1B,
                                              const float* __restrict__ w2A) {
    __shared__ float Bs[FCC][PAD];
    __shared__ float As[FCC][PAD];

    int tid   = threadIdx.x;
    int tbase = blockIdx.x * 512;
    int t0 = tbase + tid;
    int t1 = t0 + 256;
    int seg = blockIdx.y;
    int fbase0 = seg * FSEG;

    int e_first = expert_of(tbase);
    int e_last  = expert_of(tbase + 511);
    bool uni = (e_first == e_last);

    u64 zp0[8], zp1[8], a0[8], a1[8];
#pragma unroll
    for (int p = 0; p < 8; p++) { a0[p] = 0ull; a1[p] = 0ull; }
    {
        const ulonglong2* z0q = (const ulonglong2*)&g_z1[t0 * RR];
        const ulonglong2* z1q = (const ulonglong2*)&g_z1[t1 * RR];
#pragma unroll
        for (int q = 0; q < 4; q++) {
            ulonglong2 v0 = z0q[q], v1 = z1q[q];
            zp0[q * 2] = v0.x; zp0[q * 2 + 1] = v0.y;
            zp1[q * 2] = v1.x; zp1[q * 2 + 1] = v1.y;
        }
    }

    if (uni && e_first < EE) {
        for (int c = 0; c < FSEG / FCC; c++) {
            int fb = fbase0 + c * FCC;
            __syncthreads();
            {
                int f = tid;
#pragma unroll
                for (int r = 0; r < RR; r++) {
                    size_t row = (size_t)(e_first * RR + r);
                    Bs[f][r] = w1B[row * FFD + fb + f];
                    As[f][r] = w2A[row * FFD + fb + f];
                }
            }
            __syncthreads();

#pragma unroll 2
            for (int f = 0; f < FCC; f++) {
                const ulonglong2* bq = (const ulonglong2*)&Bs[f][0];
                ulonglong2 q0 = bq[0], q1 = bq[1], q2 = bq[2], q3 = bq[3];
                // token 0 preactivation
                u64 sA = ffma2(zp0[0], q0.x, 0ull);
                sA = ffma2(zp0[1], q0.y, sA);
                sA = ffma2(zp0[2], q1.x, sA);
                sA = ffma2(zp0[3], q1.y, sA);
                u64 sB = ffma2(zp0[4], q2.x, 0ull);
                sB = ffma2(zp0[5], q2.y, sB);
                sB = ffma2(zp0[6], q3.x, sB);
                sB = ffma2(zp0[7], q3.y, sB);
                // token 1 preactivation
                u64 tA = ffma2(zp1[0], q0.x, 0ull);
                tA = ffma2(zp1[1], q0.y, tA);
                tA = ffma2(zp1[2], q1.x, tA);
                tA = ffma2(zp1[3], q1.y, tA);
                u64 tB = ffma2(zp1[4], q2.x, 0ull);
                tB = ffma2(zp1[5], q2.y, tB);
                tB = ffma2(zp1[6], q3.x, tB);
                tB = ffma2(zp1[7], q3.y, tB);
                float2 va = unpack2(sA), vb = unpack2(sB);
                float2 wa = unpack2(tA), wb = unpack2(tB);
                float xa = (va.x + va.y) + (vb.x + vb.y);
                float xb = (wa.x + wa.y) + (wb.x + wb.y);
                // cheap gelu: 0.5x + t*Q(t), t = x^2 (valid |x|<=1; rare fallback)
                float ta = xa * xa, tb = xb * xb;
                float qa = fmaf(GC4, ta, GC3);
                float qb = fmaf(GC4, tb, GC3);
                qa = fmaf(qa, ta, GC2);  qb = fmaf(qb, tb, GC2);
                qa = fmaf(qa, ta, GC1);  qb = fmaf(qb, tb, GC1);
                qa = fmaf(qa, ta, GC0);  qb = fmaf(qb, tb, GC0);
                float h0 = fmaf(0.5f, xa, ta * qa);
                float h1 = fmaf(0.5f, xb, tb * qb);
                if (fmaxf(ta, tb) > 1.0f) {     // |x|>1: essentially never
                    h0 = gelu_f(xa);
                    h1 = gelu_f(xb);
                }
                u64 h02 = pack2(h0, h0);
                u64 h12 = pack2(h1, h1);
                const ulonglong2* aq = (const ulonglong2*)&As[f][0];
                ulonglong2 p0 = aq[0], p1 = aq[1], p2 = aq[2], p3 = aq[3];
                a0[0] = ffma2(h02, p0.x, a0[0]);
                a0[1] = ffma2(h02, p0.y, a0[1]);
                a0[2] = ffma2(h02, p1.x, a0[2]);
                a0[3] = ffma2(h02, p1.y, a0[3]);
                a0[4] = ffma2(h02, p2.x, a0[4]);
                a0[5] = ffma2(h02, p2.y, a0[5]);
                a0[6] = ffma2(h02, p3.x, a0[6]);
                a0[7] = ffma2(h02, p3.y, a0[7]);
                a1[0] = ffma2(h12, p0.x, a1[0]);
                a1[1] = ffma2(h12, p0.y, a1[1]);
                a1[2] = ffma2(h12, p1.x, a1[2]);
                a1[3] = ffma2(h12, p1.y, a1[3]);
                a1[4] = ffma2(h12, p2.x, a1[4]);
                a1[5] = ffma2(h12, p2.y, a1[5]);
                a1[6] = ffma2(h12, p3.x, a1[6]);
                a1[7] = ffma2(h12, p3.y, a1[7]);
            }
        }
    } else {
        // slow path (expert boundary inside block): exact gelu, direct gmem
        int ea = expert_of(t0), eb = expert_of(t1);
        float z0r[RR], z1r[RR], acc0[RR], acc1[RR];
#pragma unroll
        for (int r = 0; r < RR; r++) {
            float2 v0 = unpack2(zp0[r / 2]);
            z0r[r] = (r & 1) ? v0.y : v0.x;
            float2 v1 = unpack2(zp1[r / 2]);
            z1r[r] = (r & 1) ? v1.y : v1.x;
            acc0[r] = 0.f; acc1[r] = 0.f;
        }
        for (int f = fbase0; f < fbase0 + FSEG; f++) {
            if (ea < EE) {
                float hv = 0.f;
#pragma unroll
                for (int r = 0; r < RR; r++)
                    hv = fmaf(z0r[r], w1B[(size_t)(ea * RR + r) * FFD + f], hv);
                float h = gelu_f(hv);
#pragma unroll
                for (int r = 0; r < RR; r++)
                    acc0[r] = fmaf(h, w2A[(size_t)(ea * RR + r) * FFD + f], acc0[r]);
            }
            if (eb < EE) {
                float hv = 0.f;
#pragma unroll
                for (int r = 0; r < RR; r++)
                    hv = fmaf(z1r[r], w1B[(size_t)(eb * RR + r) * FFD + f], hv);
                float h = gelu_f(hv);
#pragma unroll
                for (int r = 0; r < RR; r++)
                    acc1[r] = fmaf(h, w2A[(size_t)(eb * RR + r) * FFD + f], acc1[r]);
            }
        }
#pragma unroll
        for (int p = 0; p < 8; p++) {
            a0[p] = pack2(acc0[2 * p], acc0[2 * p + 1]);
            a1[p] = pack2(acc1[2 * p], acc1[2 * p + 1]);
        }
    }

    {
        ulonglong2* o0 = (ulonglong2*)&g_z2p[((size_t)seg * TT + t0) * RR];
        ulonglong2* o1 = (ulonglong2*)&g_z2p[((size_t)seg * TT + t1) * RR];
#pragma unroll
        for (int q = 0; q < 4; q++) {
            ulonglong2 v0; v0.x = a0[q * 2]; v0.y = a0[q * 2 + 1];
            ulonglong2 v1; v1.x = a1[q * 2]; v1.y = a1[q * 2 + 1];
            o0[q] = v0;
            o1[q] = v1;
        }
    }
}

// ---------------- k2r: reduce segment partials ---------------------------------
__global__ __launch_bounds__(256) void k2_reduce() {
    int i = blockIdx.x * 256 + threadIdx.x;
    float4 s = *(const float4*)&g_z2[(size_t)i * 4];   // zeroed by k1
#pragma unroll
    for (int seg = 0; seg < NSEG; seg++) {
        float4 v = *(const float4*)&g_z2p[(size_t)seg * TT * RR + (size_t)i * 4];
        s.x += v.x; s.y += v.y; s.z += v.z; s.w += v.w;
    }
    *(float4*)&g_z2[(size_t)i * 4] = s;
}

// ---------------- k3: out = z2 @ B2 (float4 cols, f32x2 accum) -----------------
__global__ __launch_bounds__(256) void k3_out(const float* __restrict__ w2B,
                                              float* __restrict__ out) {
    int tok0 = blockIdx.x * 32;
    int c4   = blockIdx.y * 256 + threadIdx.x;
    __shared__ float zs[32 * RR];
    __shared__ int se[32];
    for (int i = threadIdx.x; i < 32 * RR; i += 256) zs[i] = g_z2[tok0 * RR + i];
    if (threadIdx.x < 32) se[threadIdx.x] = expert_of(tok0 + threadIdx.x);
    __syncthreads();

    int ecur = -1;
    u64 bp[RR * 2];
#pragma unroll 1
    for (int t = 0; t < 32; t++) {
        int e = se[t];
        if (e != ecur) {
            ecur = e;
            int ee = (e < EE) ? e : 0;
#pragma unroll
            for (int r = 0; r < RR; r++) {
                float4 b = *(const float4*)&w2B[(size_t)(ee * RR + r) * HH + c4 * 4];
                bp[r * 2]     = pack2(b.x, b.y);
                bp[r * 2 + 1] = pack2(b.z, b.w);
            }
        }
        u64 accA = 0ull, accB = 0ull;
#pragma unroll
        for (int r = 0; r < RR; r++) {
            float zv = zs[t * RR + r];
            u64 z2v = pack2(zv, zv);
            accA = ffma2(z2v, bp[r * 2], accA);
            accB = ffma2(z2v, bp[r * 2 + 1], accB);
        }
        float2 ra = unpack2(accA), rb = unpack2(accB);
        float4 o = make_float4(ra.x, ra.y, rb.x, rb.y);
        *(float4*)&out[(size_t)(tok0 + t) * HH + c4 * 4] = o;
    }
}

// ---------------- launch --------------------------------------------------------
extern "C" void kernel_launch(void* const* d_in, const int* in_sizes, int n_in,
                              void* d_out, int out_size) {
    const float* x   = (const float*)d_in[0];
    const void*  tpe = (const void*)d_in[1];
    const float* w1A = (const float*)d_in[2];
    const float* w1B = (const float*)d_in[3];
    const float* w2A = (const float*)d_in[4];
    const float* w2B = (const float*)d_in[5];
    float* out = (float*)d_out;

    k0_bounds<<<1, 32>>>(tpe);

    k1_z1<<<TT / K1_TOK, 256>>>(x, w1A);

    dim3 g2(TT / 512, NSEG);
    k2_mid<<<g2, 256>>>(w1B, w2A);

    k2_reduce<<<(TT * RR / 4) / 256, 256>>>();

    dim3 g3(TT / 32, HH / 1024);
    k3_out<<<g3, 256>>>(w2B, out);
}

// round 7
// speedup vs baseline: 3.0776x; 1.3210x over previous
#include <cuda_runtime.h>
#include <cuda_fp16.h>
#include <cstdint>

#define TT 16384
#define HH 2048
#define FFD 8192
#define EE 8
#define RR 16

#define NC 64                    // f-chunk width
#define NCHUNK (FFD / NC)        // 128
#define MT 128                   // token tile per CTA

#define K1_TOK 128
#define K1_KC  64
#define K1_PADX 4

typedef unsigned long long u64;

// ---------------- scratch ------------------------------------------------------
__device__ float g_z1[TT * RR];                 // 1 MB
__device__ float g_z2[TT * RR];                 // 1 MB
__device__ float g_M[EE * RR * RR];             // per-expert 0.5*B1@A2^T
__device__ long long g_off[EE + 1];

// ---------------- scalar helpers ----------------------------------------------
__device__ __forceinline__ u64 ffma2(u64 a, u64 b, u64 c) {
    u64 d;
    asm("fma.rn.f32x2 %0, %1, %2, %3;" : "=l"(d) : "l"(a), "l"(b), "l"(c));
    return d;
}
__device__ __forceinline__ u64 pack2(float x, float y) {
    u64 r;
    asm("mov.b64 %0, {%1, %2};" : "=l"(r) : "f"(x), "f"(y));
    return r;
}
__device__ __forceinline__ float2 unpack2(u64 v) {
    float2 r;
    asm("mov.b64 {%0, %1}, %2;" : "=f"(r.x), "=f"(r.y) : "l"(v));
    return r;
}

// exact gelu (A&S 7.1.26 erf) — slow paths / rare fallback
__device__ __forceinline__ float gelu_f(float x) {
    float ax = fabsf(x) * 0.7071067811865475f;
    float t  = __fdividef(1.0f, fmaf(0.3275911f, ax, 1.0f));
    float p  = fmaf(t, 1.061405429f, -1.453152027f);
    p = fmaf(p, t, 1.421413741f);
    p = fmaf(p, t, -0.284496736f);
    p = fmaf(p, t, 0.254829592f);
    p *= t;
    float ex = __expf(-ax * ax);
    float er = fmaf(-p, ex, 1.0f);
    er = copysignf(er, x);
    return 0.5f * x * (1.0f + er);
}

// G(x) = gelu(x) - 0.5x = t*Q(t), t=x^2; degree-4 Q valid |x|<=1 (abs err <= 9.4e-6)
#define GC0 0.3989422804014327f
#define GC1 (-0.06649038006690545f)
#define GC2 0.009973557010035818f
#define GC3 (-0.0011873282154804544f)
#define GC4 0.00011543701400504418f

__device__ __forceinline__ int expert_of(int t) {
    int e = 0;
#pragma unroll
    for (int i = 1; i <= EE; i++)
        if ((long long)t >= g_off[i]) e = i;
    return e;
}

// m16n8k16 fp16 MMA, fp32 accum (baseline PTX — legal on plain sm_103)
__device__ __forceinline__ void mma16816(float* d, const uint32_t* a,
                                         const uint32_t* b, const float* c) {
    asm volatile(
        "mma.sync.aligned.m16n8k16.row.col.f32.f16.f16.f32 "
        "{%0,%1,%2,%3}, {%4,%5,%6,%7}, {%8,%9}, {%10,%11,%12,%13};"
        : "=f"(d[0]), "=f"(d[1]), "=f"(d[2]), "=f"(d[3])
        : "r"(a[0]), "r"(a[1]), "r"(a[2]), "r"(a[3]),
          "r"(b[0]), "r"(b[1]),
          "f"(c[0]), "f"(c[1]), "f"(c[2]), "f"(c[3]));
}
__device__ __forceinline__ uint32_t h2u(__half2 h) { return *(uint32_t*)&h; }

// ---------------- k0: bounds (dtype-agnostic int32/int64) ----------------------
__global__ void k0_bounds(const void* __restrict__ tpe_raw) {
    if (threadIdx.x == 0) {
        const int* p32 = (const int*)tpe_raw;
        long long s32 = 0;
#pragma unroll
        for (int i = 0; i < EE; i++) s32 += (long long)p32[i];
        long long a = 0;
        g_off[0] = 0;
        if (s32 == (long long)TT) {
#pragma unroll
            for (int i = 0; i < EE; i++) { a += (long long)p32[i]; g_off[i + 1] = a; }
        } else {
            const long long* p64 = (const long long*)tpe_raw;
#pragma unroll
            for (int i = 0; i < EE; i++) { a += p64[i]; g_off[i + 1] = a; }
        }
    }
}

// ---------------- k_lin: g_M[e][r1][r2] = 0.5 * sum_f B1[r1][f]*A2[r2][f] ------
__global__ __launch_bounds__(256) void k_lin(const float* __restrict__ w1B,
                                             const float* __restrict__ w2A) {
    __shared__ float red[256 * RR];
    int e  = blockIdx.x >> 4;
    int r1 = blockIdx.x & 15;
    const float* b1 = w1B + (size_t)(e * RR + r1) * FFD;
    const float* a2 = w2A + (size_t)e * RR * FFD;
    float acc[RR];
#pragma unroll
    for (int r = 0; r < RR; r++) acc[r] = 0.f;
    for (int f = threadIdx.x; f < FFD; f += 256) {
        float bv = b1[f];
#pragma unroll
        for (int r2 = 0; r2 < RR; r2++)
            acc[r2] = fmaf(bv, a2[(size_t)r2 * FFD + f], acc[r2]);
    }
#pragma unroll
    for (int r = 0; r < RR; r++) red[threadIdx.x * RR + r] = acc[r];
    __syncthreads();
    for (int off = 128; off > 0; off >>= 1) {
        if (threadIdx.x < off) {
#pragma unroll
            for (int r = 0; r < RR; r++)
                red[threadIdx.x * RR + r] += red[(threadIdx.x + off) * RR + r];
        }
        __syncthreads();
    }
    if (threadIdx.x < RR)
        g_M[(e * RR + r1) * RR + threadIdx.x] = 0.5f * red[threadIdx.x];
}

// ---------------- k1: z1 = x @ A1^T (smem-tiled, reg-prefetch) -----------------
__global__ __launch_bounds__(256) void k1_z1(const float* __restrict__ x,
                                             const float* __restrict__ w1A) {
    __shared__ float xs[K1_TOK][K1_KC + K1_PADX];
    __shared__ float as_[RR][K1_KC];
    __shared__ float part[K1_TOK][RR];

    int tid  = threadIdx.x;
    int lt   = tid & 127;
    int half = tid >> 7;
    int tok0 = blockIdx.x * K1_TOK;
    int token = tok0 + lt;

    int e_first = expert_of(tok0);
    int e_last  = expert_of(tok0 + K1_TOK - 1);
    bool uni = (e_first == e_last);

    u64 acc2[RR];
#pragma unroll
    for (int r = 0; r < RR; r++) acc2[r] = 0ull;

    if (uni && e_first < EE) {
        const float* arow = w1A + (size_t)e_first * RR * HH;
        float4 px[8], pa;
#pragma unroll
        for (int j = 0; j < 8; j++) {
            int idx = tid + j * 256;
            int row = idx >> 4, c4 = idx & 15;
            px[j] = *(const float4*)&x[(size_t)(tok0 + row) * HH + c4 * 4];
        }
        {
            int row = tid >> 4, c4 = tid & 15;
            pa = *(const float4*)&arow[(size_t)row * HH + c4 * 4];
        }
        int kb = half * (K1_KC / 2);

        for (int c = 0; c < HH / K1_KC; c++) {
            __syncthreads();
#pragma unroll
            for (int j = 0; j < 8; j++) {
                int idx = tid + j * 256;
                int row = idx >> 4, c4 = idx & 15;
                *(float4*)&xs[row][c4 * 4] = px[j];
            }
            {
                int row = tid >> 4, c4 = tid & 15;
                *(float4*)&as_[row][c4 * 4] = pa;
            }
            __syncthreads();
            if (c + 1 < HH / K1_KC) {
                int kc = (c + 1) * K1_KC;
#pragma unroll
                for (int j = 0; j < 8; j++) {
                    int idx = tid + j * 256;
                    int row = idx >> 4, c4 = idx & 15;
                    px[j] = *(const float4*)&x[(size_t)(tok0 + row) * HH + kc + c4 * 4];
                }
                {
                    int row = tid >> 4, c4 = tid & 15;
                    pa = *(const float4*)&arow[(size_t)row * HH + kc + c4 * 4];
                }
            }
#pragma unroll 4
            for (int kp = 0; kp < 16; kp++) {
                int k = kb + kp * 2;
                u64 xv = *(const u64*)&xs[lt][k];
#pragma unroll
                for (int r = 0; r < RR; r++) {
                    u64 av = *(const u64*)&as_[r][k];
                    acc2[r] = ffma2(xv, av, acc2[r]);
                }
            }
        }
    } else {
        int e = expert_of(token);
        if (e < EE) {
            const float* xrow = x + (size_t)token * HH;
            const float* arow = w1A + (size_t)e * RR * HH;
            for (int k = half * 1024; k < half * 1024 + 1024; k += 2) {
                u64 xv = pack2(xrow[k], xrow[k + 1]);
#pragma unroll
                for (int r = 0; r < RR; r++) {
                    u64 av = pack2(__ldg(&arow[(size_t)r * HH + k]),
                                   __ldg(&arow[(size_t)r * HH + k + 1]));
                    acc2[r] = ffma2(xv, av, acc2[r]);
                }
            }
        }
    }

    __syncthreads();
    if (half == 1) {
#pragma unroll
        for (int r = 0; r < RR; r++) {
            float2 v = unpack2(acc2[r]);
            part[lt][r] = v.x + v.y;
        }
    }
    __syncthreads();
    if (half == 0) {
#pragma unroll
        for (int i = 0; i < 4; i++) {
            float4 o;
            float2 v0 = unpack2(acc2[i * 4 + 0]);
            float2 v1 = unpack2(acc2[i * 4 + 1]);
            float2 v2 = unpack2(acc2[i * 4 + 2]);
            float2 v3 = unpack2(acc2[i * 4 + 3]);
            o.x = v0.x + v0.y + part[lt][i * 4 + 0];
            o.y = v1.x + v1.y + part[lt][i * 4 + 1];
            o.z = v2.x + v2.y + part[lt][i * 4 + 2];
            o.w = v3.x + v3.y + part[lt][i * 4 + 3];
            *(float4*)&g_z1[token * RR + i * 4] = o;
        }
    }
}

// ---------------- k2: fused middle via warp MMA (HMMA) -------------------------
// z2 = z1 @ M_e  +  G(z1 @ B1) @ A2^T
// 8 warps/CTA, 16 tokens/warp; FF in 64-wide chunks, double-buffered smem.
// smem: sb1[2][f=64][r=16 pad 24] fp16 (B-frag reads contiguous in r)
//       sa2[2][r=16][f=64 pad 72] fp16 (B-frag reads contiguous in f)
__global__ __launch_bounds__(256) void k2_mma(const float* __restrict__ w1B,
                                              const float* __restrict__ w2A) {
    __shared__ __half sb1[2][64][24];
    __shared__ __half sa2[2][16][72];
    __shared__ float sM[RR * RR];

    int tid  = threadIdx.x;
    int warp = tid >> 5, lane = tid & 31;
    int tok0 = blockIdx.x * MT;

    int e_first = expert_of(tok0);
    int e_last  = expert_of(tok0 + MT - 1);
    bool uni = (e_first == e_last);

    if (!uni) {
        // slow path: exact fp32 per token (expert boundary inside tile)
        if (tid < MT) {
            int token = tok0 + tid;
            int e = expert_of(token);
            float acc[RR];
#pragma unroll
            for (int r = 0; r < RR; r++) acc[r] = 0.f;
            if (e < EE) {
                float zr[RR];
#pragma unroll
                for (int r = 0; r < RR; r++) zr[r] = g_z1[token * RR + r];
                const float* b1 = w1B + (size_t)e * RR * FFD;
                const float* a2 = w2A + (size_t)e * RR * FFD;
                for (int f = 0; f < FFD; f++) {
                    float hv = 0.f;
#pragma unroll
                    for (int r = 0; r < RR; r++)
                        hv = fmaf(zr[r], b1[(size_t)r * FFD + f], hv);
                    float h = gelu_f(hv);
#pragma unroll
                    for (int r = 0; r < RR; r++)
                        acc[r] = fmaf(h, a2[(size_t)r * FFD + f], acc[r]);
                }
            }
#pragma unroll
            for (int r = 0; r < RR; r++) g_z2[token * RR + r] = acc[r];
        }
        return;
    }
    if (e_first >= EE) {
        if (tid < MT) {
#pragma unroll
            for (int i = 0; i < 4; i++)
                *(float4*)&g_z2[(tok0 + tid) * RR + i * 4] =
                    make_float4(0.f, 0.f, 0.f, 0.f);
        }
        return;
    }

    // ---- fast path ----
    int e = e_first;
    const float* b1g = w1B + (size_t)e * RR * FFD;
    const float* a2g = w2A + (size_t)e * RR * FFD;

    sM[tid & 255] = g_M[e * 256 + (tid & 255)];

    // z1 A-fragment (m16k16): rows = warp tokens, cols = rank
    int mrow = warp * 16 + (lane >> 2);
    int kcol = (lane & 3) * 2;
    uint32_t za[4];
    {
        float2 v00 = *(const float2*)&g_z1[(tok0 + mrow) * RR + kcol];
        float2 v10 = *(const float2*)&g_z1[(tok0 + mrow + 8) * RR + kcol];
        float2 v01 = *(const float2*)&g_z1[(tok0 + mrow) * RR + kcol + 8];
        float2 v11 = *(const float2*)&g_z1[(tok0 + mrow + 8) * RR + kcol + 8];
        za[0] = h2u(__floats2half2_rn(v00.x, v00.y));
        za[1] = h2u(__floats2half2_rn(v10.x, v10.y));
        za[2] = h2u(__floats2half2_rn(v01.x, v01.y));
        za[3] = h2u(__floats2half2_rn(v11.x, v11.y));
    }

    // stage chunk 0 into buf 0
    {
#pragma unroll
        for (int i = 0; i < 4; i++) {
            int idx = tid + i * 256;                 // 0..1023
            int r = idx >> 6, f = idx & 63;
            sb1[0][f][r] = __float2half_rn(b1g[(size_t)r * FFD + f]);
        }
#pragma unroll
        for (int i = 0; i < 2; i++) {
            int idx = tid + i * 256;                 // 0..511
            int r = idx >> 5, f2 = idx & 31;
            float2 v = *(const float2*)&a2g[(size_t)r * FFD + f2 * 2];
            *(__half2*)&sa2[0][r][f2 * 2] = __floats2half2_rn(v.x, v.y);
        }
    }
    __syncthreads();

    float zacc[2][4];
#pragma unroll
    for (int j = 0; j < 2; j++)
#pragma unroll
        for (int q = 0; q < 4; q++) zacc[j][q] = 0.f;

    for (int c = 0; c < NCHUNK; c++) {
        int cur = c & 1, nxt = cur ^ 1;
        bool have_next = (c + 1 < NCHUNK);

        // prefetch next chunk into regs
        float pb[4];
        float2 pa[2];
        if (have_next) {
            int fb = (c + 1) * NC;
#pragma unroll
            for (int i = 0; i < 4; i++) {
                int idx = tid + i * 256;
                pb[i] = b1g[(size_t)(idx >> 6) * FFD + fb + (idx & 63)];
            }
#pragma unroll
            for (int i = 0; i < 2; i++) {
                int idx = tid + i * 256;
                pa[i] = *(const float2*)&a2g[(size_t)(idx >> 5) * FFD + fb + (idx & 31) * 2];
            }
        }

        // GEMM1: hpre[16 tok, 64 f] = z1 @ B1chunk
        float c1[8][4];
#pragma unroll
        for (int j = 0; j < 8; j++) {
            uint32_t bf[2];
            bf[0] = *(const uint32_t*)&sb1[cur][8 * j + (lane >> 2)][kcol];
            bf[1] = *(const uint32_t*)&sb1[cur][8 * j + (lane >> 2)][kcol + 8];
            float zero4[4] = {0.f, 0.f, 0.f, 0.f};
            mma16816(c1[j], za, bf, zero4);
        }

        // G elementwise + pack C-frags into A-frags for GEMM2
        uint32_t ga[4][4];
        float tmax = 0.f;
#pragma unroll
        for (int j = 0; j < 8; j++) {
#pragma unroll
            for (int q = 0; q < 2; q++) {
                float x0 = c1[j][2 * q], x1 = c1[j][2 * q + 1];
                u64 xv = pack2(x0, x1);
                u64 tv = ffma2(xv, xv, 0ull);
                u64 qv = ffma2(pack2(GC4, GC4), tv, pack2(GC3, GC3));
                qv = ffma2(qv, tv, pack2(GC2, GC2));
                qv = ffma2(qv, tv, pack2(GC1, GC1));
                qv = ffma2(qv, tv, pack2(GC0, GC0));
                u64 gv = ffma2(tv, qv, 0ull);
                float2 tf = unpack2(tv);
                tmax = fmaxf(tmax, fmaxf(tf.x, tf.y));
                float2 gf = unpack2(gv);
                ga[j >> 1][(j & 1) * 2 + q] = h2u(__floats2half2_rn(gf.x, gf.y));
            }
        }
        if (tmax > 1.0f) {             // |x|>1: exact fallback (data |x|<~0.6)
#pragma unroll
            for (int j = 0; j < 8; j++) {
#pragma unroll
                for (int q = 0; q < 2; q++) {
                    float x0 = c1[j][2 * q], x1 = c1[j][2 * q + 1];
                    float g0 = gelu_f(x0) - 0.5f * x0;
                    float g1 = gelu_f(x1) - 0.5f * x1;
                    ga[j >> 1][(j & 1) * 2 + q] = h2u(__floats2half2_rn(g0, g1));
                }
            }
        }

        // GEMM2: zacc += G @ A2chunk^T  (K=64 in 4 steps, N=16 in 2 tiles)
#pragma unroll
        for (int j = 0; j < 2; j++) {
#pragma unroll
            for (int s = 0; s < 4; s++) {
                uint32_t bf[2];
                bf[0] = *(const uint32_t*)&sa2[cur][8 * j + (lane >> 2)][16 * s + kcol];
                bf[1] = *(const uint32_t*)&sa2[cur][8 * j + (lane >> 2)][16 * s + kcol + 8];
                mma16816(zacc[j], ga[s], bf, zacc[j]);
            }
        }

        // commit prefetched regs into the other buffer
        if (have_next) {
#pragma unroll
            for (int i = 0; i < 4; i++) {
                int idx = tid + i * 256;
                sb1[nxt][idx & 63][idx >> 6] = __float2half_rn(pb[i]);
            }
#pragma unroll
            for (int i = 0; i < 2; i++) {
                int idx = tid + i * 256;
                *(__half2*)&sa2[nxt][idx >> 5][(idx & 31) * 2] =
                    __floats2half2_rn(pa[i].x, pa[i].y);
            }
        }
        __syncthreads();
    }

    // epilogue: z2 = zacc + z1 @ M_e
    {
        int t0 = tok0 + mrow, t1 = t0 + 8;
        float z1a[RR], z1b[RR];
#pragma unroll
        for (int i = 0; i < 4; i++) {
            float4 v = *(const float4*)&g_z1[(size_t)t0 * RR + i * 4];
            float4 w = *(const float4*)&g_z1[(size_t)t1 * RR + i * 4];
            z1a[i * 4 + 0] = v.x; z1a[i * 4 + 1] = v.y;
            z1a[i * 4 + 2] = v.z; z1a[i * 4 + 3] = v.w;
            z1b[i * 4 + 0] = w.x; z1b[i * 4 + 1] = w.y;
            z1b[i * 4 + 2] = w.z; z1b[i * 4 + 3] = w.w;
        }
#pragma unroll
        for (int j = 0; j < 2; j++) {
            u64 accq[2];
#pragma unroll
            for (int q = 0; q < 2; q++) {
                int r2 = 8 * j + kcol + q;
                u64 acc = pack2(zacc[j][q], zacc[j][q + 2]);   // (row0, row1)
#pragma unroll
                for (int r1 = 0; r1 < RR; r1++) {
                    float m = sM[r1 * RR + r2];
                    acc = ffma2(pack2(z1a[r1], z1b[r1]), pack2(m, m), acc);
                }
                accq[q] = acc;
            }
            float2 a0 = unpack2(accq[0]), a1 = unpack2(accq[1]);
            *(float2*)&g_z2[(size_t)t0 * RR + 8 * j + kcol] = make_float2(a0.x, a1.x);
            *(float2*)&g_z2[(size_t)t1 * RR + 8 * j + kcol] = make_float2(a0.y, a1.y);
        }
    }
}

// ---------------- k3: out = z2 @ B2 --------------------------------------------
__global__ __launch_bounds__(256) void k3_out(const float* __restrict__ w2B,
                                              float* __restrict__ out) {
    int tok0 = blockIdx.x * 32;
    int c4   = blockIdx.y * 256 + threadIdx.x;
    __shared__ float zs[32 * RR];
    __shared__ int se[32];
    for (int i = threadIdx.x; i < 32 * RR; i += 256) zs[i] = g_z2[tok0 * RR + i];
    if (threadIdx.x < 32) se[threadIdx.x] = expert_of(tok0 + threadIdx.x);
    __syncthreads();

    int ecur = -1;
    u64 bp[RR * 2];
#pragma unroll 1
    for (int t = 0; t < 32; t++) {
        int e = se[t];
        if (e != ecur) {
            ecur = e;
            int ee = (e < EE) ? e : 0;
#pragma unroll
            for (int r = 0; r < RR; r++) {
                float4 b = *(const float4*)&w2B[(size_t)(ee * RR + r) * HH + c4 * 4];
                bp[r * 2]     = pack2(b.x, b.y);
                bp[r * 2 + 1] = pack2(b.z, b.w);
            }
        }
        u64 accA = 0ull, accB = 0ull;
#pragma unroll
        for (int r = 0; r < RR; r++) {
            float zv = zs[t * RR + r];
            u64 z2v = pack2(zv, zv);
            accA = ffma2(z2v, bp[r * 2], accA);
            accB = ffma2(z2v, bp[r * 2 + 1], accB);
        }
        float2 ra = unpack2(accA), rb = unpack2(accB);
        float4 o = make_float4(ra.x, ra.y, rb.x, rb.y);
        *(float4*)&out[(size_t)(tok0 + t) * HH + c4 * 4] = o;
    }
}

// ---------------- launch --------------------------------------------------------
extern "C" void kernel_launch(void* const* d_in, const int* in_sizes, int n_in,
                              void* d_out, int out_size) {
    const float* x   = (const float*)d_in[0];
    const void*  tpe = (const void*)d_in[1];
    const float* w1A = (const float*)d_in[2];
    const float* w1B = (const float*)d_in[3];
    const float* w2A = (const float*)d_in[4];
    const float* w2B = (const float*)d_in[5];
    float* out = (float*)d_out;

    k0_bounds<<<1, 32>>>(tpe);

    k_lin<<<EE * RR, 256>>>(w1B, w2A);

    k1_z1<<<TT / K1_TOK, 256>>>(x, w1A);

    k2_mma<<<TT / MT, 256>>>(w1B, w2A);

    dim3 g3(TT / 32, HH / 1024);
    k3_out<<<g3, 256>>>(w2B, out);
}

// round 8
// speedup vs baseline: 3.4957x; 1.1358x over previous
#include <cuda_runtime.h>
#include <cuda_fp16.h>
#include <cstdint>

#define TT 16384
#define HH 2048
#define FFD 8192
#define EE 8
#define RR 16

#define NC 64                    // f-chunk width
#define NSEG 2                   // FF segments (CTA-parallel)
#define NCHUNK_SEG (FFD / NC / NSEG)   // 64 chunks per segment
#define MT 128                   // token tile per CTA

#define K1_TOK 128
#define K1_KC  64
#define K1_PADX 4

typedef unsigned long long u64;

// ---------------- scratch ------------------------------------------------------
__device__ float g_z1[TT * RR];                 // 1 MB
__device__ float g_z2p[NSEG * TT * RR];         // 2 MB (per-FF-segment partials)
__device__ float g_M[EE * RR * RR];             // per-expert 0.5*B1@A2^T
__device__ long long g_off[EE + 1];

// ---------------- scalar helpers ----------------------------------------------
__device__ __forceinline__ u64 ffma2(u64 a, u64 b, u64 c) {
    u64 d;
    asm("fma.rn.f32x2 %0, %1, %2, %3;" : "=l"(d) : "l"(a), "l"(b), "l"(c));
    return d;
}
__device__ __forceinline__ u64 pack2(float x, float y) {
    u64 r;
    asm("mov.b64 %0, {%1, %2};" : "=l"(r) : "f"(x), "f"(y));
    return r;
}
__device__ __forceinline__ float2 unpack2(u64 v) {
    float2 r;
    asm("mov.b64 {%0, %1}, %2;" : "=f"(r.x), "=f"(r.y) : "l"(v));
    return r;
}

// exact gelu (A&S 7.1.26 erf) — slow paths / rare fallback
__device__ __forceinline__ float gelu_f(float x) {
    float ax = fabsf(x) * 0.7071067811865475f;
    float t  = __fdividef(1.0f, fmaf(0.3275911f, ax, 1.0f));
    float p  = fmaf(t, 1.061405429f, -1.453152027f);
    p = fmaf(p, t, 1.421413741f);
    p = fmaf(p, t, -0.284496736f);
    p = fmaf(p, t, 0.254829592f);
    p *= t;
    float ex = __expf(-ax * ax);
    float er = fmaf(-p, ex, 1.0f);
    er = copysignf(er, x);
    return 0.5f * x * (1.0f + er);
}

// G(x) = gelu(x) - 0.5x = t*Q(t), t=x^2; degree-4 Q valid |x|<=1 (abs err <= 9.4e-6)
#define GC0 0.3989422804014327f
#define GC1 (-0.06649038006690545f)
#define GC2 0.009973557010035818f
#define GC3 (-0.0011873282154804544f)
#define GC4 0.00011543701400504418f

__device__ __forceinline__ int expert_of(int t) {
    int e = 0;
#pragma unroll
    for (int i = 1; i <= EE; i++)
        if ((long long)t >= g_off[i]) e = i;
    return e;
}

// m16n8k16 fp16 MMA, fp32 accum (baseline PTX — legal on plain sm_103)
__device__ __forceinline__ void mma16816(float* d, const uint32_t* a,
                                         const uint32_t* b, const float* c) {
    asm volatile(
        "mma.sync.aligned.m16n8k16.row.col.f32.f16.f16.f32 "
        "{%0,%1,%2,%3}, {%4,%5,%6,%7}, {%8,%9}, {%10,%11,%12,%13};"
        : "=f"(d[0]), "=f"(d[1]), "=f"(d[2]), "=f"(d[3])
        : "r"(a[0]), "r"(a[1]), "r"(a[2]), "r"(a[3]),
          "r"(b[0]), "r"(b[1]),
          "f"(c[0]), "f"(c[1]), "f"(c[2]), "f"(c[3]));
}
__device__ __forceinline__ uint32_t h2u(__half2 h) { return *(uint32_t*)&h; }

// ---------------- k0: bounds (dtype-agnostic int32/int64) ----------------------
__global__ void k0_bounds(const void* __restrict__ tpe_raw) {
    if (threadIdx.x == 0) {
        const int* p32 = (const int*)tpe_raw;
        long long s32 = 0;
#pragma unroll
        for (int i = 0; i < EE; i++) s32 += (long long)p32[i];
        long long a = 0;
        g_off[0] = 0;
        if (s32 == (long long)TT) {
#pragma unroll
            for (int i = 0; i < EE; i++) { a += (long long)p32[i]; g_off[i + 1] = a; }
        } else {
            const long long* p64 = (const long long*)tpe_raw;
#pragma unroll
            for (int i = 0; i < EE; i++) { a += p64[i]; g_off[i + 1] = a; }
        }
    }
}

// ---------------- k_lin: g_M[e][r1][r2] = 0.5 * sum_f B1[r1][f]*A2[r2][f] ------
__global__ __launch_bounds__(256) void k_lin(const float* __restrict__ w1B,
                                             const float* __restrict__ w2A) {
    __shared__ float red[256 * RR];
    int e  = blockIdx.x >> 4;
    int r1 = blockIdx.x & 15;
    const float* b1 = w1B + (size_t)(e * RR + r1) * FFD;
    const float* a2 = w2A + (size_t)e * RR * FFD;
    float acc[RR];
#pragma unroll
    for (int r = 0; r < RR; r++) acc[r] = 0.f;
    for (int f = threadIdx.x; f < FFD; f += 256) {
        float bv = b1[f];
#pragma unroll
        for (int r2 = 0; r2 < RR; r2++)
            acc[r2] = fmaf(bv, a2[(size_t)r2 * FFD + f], acc[r2]);
    }
#pragma unroll
    for (int r = 0; r < RR; r++) red[threadIdx.x * RR + r] = acc[r];
    __syncthreads();
    for (int off = 128; off > 0; off >>= 1) {
        if (threadIdx.x < off) {
#pragma unroll
            for (int r = 0; r < RR; r++)
                red[threadIdx.x * RR + r] += red[(threadIdx.x + off) * RR + r];
        }
        __syncthreads();
    }
    if (threadIdx.x < RR)
        g_M[(e * RR + r1) * RR + threadIdx.x] = 0.5f * red[threadIdx.x];
}

// ---------------- k1: z1 = x @ A1^T (smem-tiled, reg-prefetch) -----------------
__global__ __launch_bounds__(256) void k1_z1(const float* __restrict__ x,
                                             const float* __restrict__ w1A) {
    __shared__ float xs[K1_TOK][K1_KC + K1_PADX];
    __shared__ float as_[RR][K1_KC];
    __shared__ float part[K1_TOK][RR];

    int tid  = threadIdx.x;
    int lt   = tid & 127;
    int half = tid >> 7;
    int tok0 = blockIdx.x * K1_TOK;
    int token = tok0 + lt;

    int e_first = expert_of(tok0);
    int e_last  = expert_of(tok0 + K1_TOK - 1);
    bool uni = (e_first == e_last);

    u64 acc2[RR];
#pragma unroll
    for (int r = 0; r < RR; r++) acc2[r] = 0ull;

    if (uni && e_first < EE) {
        const float* arow = w1A + (size_t)e_first * RR * HH;
        float4 px[8], pa;
#pragma unroll
        for (int j = 0; j < 8; j++) {
            int idx = tid + j * 256;
            int row = idx >> 4, c4 = idx & 15;
            px[j] = *(const float4*)&x[(size_t)(tok0 + row) * HH + c4 * 4];
        }
        {
            int row = tid >> 4, c4 = tid & 15;
            pa = *(const float4*)&arow[(size_t)row * HH + c4 * 4];
        }
        int kb = half * (K1_KC / 2);

        for (int c = 0; c < HH / K1_KC; c++) {
            __syncthreads();
#pragma unroll
            for (int j = 0; j < 8; j++) {
                int idx = tid + j * 256;
                int row = idx >> 4, c4 = idx & 15;
                *(float4*)&xs[row][c4 * 4] = px[j];
            }
            {
                int row = tid >> 4, c4 = tid & 15;
                *(float4*)&as_[row][c4 * 4] = pa;
            }
            __syncthreads();
            if (c + 1 < HH / K1_KC) {
                int kc = (c + 1) * K1_KC;
#pragma unroll
                for (int j = 0; j < 8; j++) {
                    int idx = tid + j * 256;
                    int row = idx >> 4, c4 = idx & 15;
                    px[j] = *(const float4*)&x[(size_t)(tok0 + row) * HH + kc + c4 * 4];
                }
                {
                    int row = tid >> 4, c4 = tid & 15;
                    pa = *(const float4*)&arow[(size_t)row * HH + kc + c4 * 4];
                }
            }
#pragma unroll 4
            for (int kp = 0; kp < 16; kp++) {
                int k = kb + kp * 2;
                u64 xv = *(const u64*)&xs[lt][k];
#pragma unroll
                for (int r = 0; r < RR; r++) {
                    u64 av = *(const u64*)&as_[r][k];
                    acc2[r] = ffma2(xv, av, acc2[r]);
                }
            }
        }
    } else {
        int e = expert_of(token);
        if (e < EE) {
            const float* xrow = x + (size_t)token * HH;
            const float* arow = w1A + (size_t)e * RR * HH;
            for (int k = half * 1024; k < half * 1024 + 1024; k += 2) {
                u64 xv = pack2(xrow[k], xrow[k + 1]);
#pragma unroll
                for (int r = 0; r < RR; r++) {
                    u64 av = pack2(__ldg(&arow[(size_t)r * HH + k]),
                                   __ldg(&arow[(size_t)r * HH + k + 1]));
                    acc2[r] = ffma2(xv, av, acc2[r]);
                }
            }
        }
    }

    __syncthreads();
    if (half == 1) {
#pragma unroll
        for (int r = 0; r < RR; r++) {
            float2 v = unpack2(acc2[r]);
            part[lt][r] = v.x + v.y;
        }
    }
    __syncthreads();
    if (half == 0) {
#pragma unroll
        for (int i = 0; i < 4; i++) {
            float4 o;
            float2 v0 = unpack2(acc2[i * 4 + 0]);
            float2 v1 = unpack2(acc2[i * 4 + 1]);
            float2 v2 = unpack2(acc2[i * 4 + 2]);
            float2 v3 = unpack2(acc2[i * 4 + 3]);
            o.x = v0.x + v0.y + part[lt][i * 4 + 0];
            o.y = v1.x + v1.y + part[lt][i * 4 + 1];
            o.z = v2.x + v2.y + part[lt][i * 4 + 2];
            o.w = v3.x + v3.y + part[lt][i * 4 + 3];
            *(float4*)&g_z1[token * RR + i * 4] = o;
        }
    }
}

// ---------------- k2: fused middle via warp MMA, FF split over NSEG CTAs -------
// z2p[seg] = (seg==0 ? z1 @ M_e : 0) + G(z1 @ B1seg) @ A2seg^T
__global__ __launch_bounds__(256) void k2_mma(const float* __restrict__ w1B,
                                              const float* __restrict__ w2A) {
    __shared__ __half sb1[2][64][24];
    __shared__ __half sa2[2][16][72];
    __shared__ float sM[RR * RR];

    int tid  = threadIdx.x;
    int warp = tid >> 5, lane = tid & 31;
    int tok0 = blockIdx.x * MT;
    int seg  = blockIdx.y;
    int c0   = seg * NCHUNK_SEG;
    float* z2o = g_z2p + (size_t)seg * TT * RR;

    int e_first = expert_of(tok0);
    int e_last  = expert_of(tok0 + MT - 1);
    bool uni = (e_first == e_last);

    if (!uni) {
        // slow path: exact fp32 per token over this segment's f range
        if (tid < MT) {
            int token = tok0 + tid;
            int e = expert_of(token);
            float acc[RR];
#pragma unroll
            for (int r = 0; r < RR; r++) acc[r] = 0.f;
            if (e < EE) {
                float zr[RR];
#pragma unroll
                for (int r = 0; r < RR; r++) zr[r] = g_z1[token * RR + r];
                const float* b1 = w1B + (size_t)e * RR * FFD;
                const float* a2 = w2A + (size_t)e * RR * FFD;
                int f0 = c0 * NC, f1 = f0 + NCHUNK_SEG * NC;
                for (int f = f0; f < f1; f++) {
                    float hv = 0.f;
#pragma unroll
                    for (int r = 0; r < RR; r++)
                        hv = fmaf(zr[r], b1[(size_t)r * FFD + f], hv);
                    float h = gelu_f(hv);
#pragma unroll
                    for (int r = 0; r < RR; r++)
                        acc[r] = fmaf(h, a2[(size_t)r * FFD + f], acc[r]);
                }
            }
#pragma unroll
            for (int r = 0; r < RR; r++) z2o[token * RR + r] = acc[r];
        }
        return;
    }
    if (e_first >= EE) {
        if (tid < MT) {
#pragma unroll
            for (int i = 0; i < 4; i++)
                *(float4*)&z2o[(size_t)(tok0 + tid) * RR + i * 4] =
                    make_float4(0.f, 0.f, 0.f, 0.f);
        }
        return;
    }

    // ---- fast path ----
    int e = e_first;
    const float* b1g = w1B + (size_t)e * RR * FFD;
    const float* a2g = w2A + (size_t)e * RR * FFD;

    sM[tid & 255] = g_M[e * 256 + (tid & 255)];

    // z1 A-fragment (m16k16)
    int mrow = warp * 16 + (lane >> 2);
    int kcol = (lane & 3) * 2;
    uint32_t za[4];
    {
        float2 v00 = *(const float2*)&g_z1[(tok0 + mrow) * RR + kcol];
        float2 v10 = *(const float2*)&g_z1[(tok0 + mrow + 8) * RR + kcol];
        float2 v01 = *(const float2*)&g_z1[(tok0 + mrow) * RR + kcol + 8];
        float2 v11 = *(const float2*)&g_z1[(tok0 + mrow + 8) * RR + kcol + 8];
        za[0] = h2u(__floats2half2_rn(v00.x, v00.y));
        za[1] = h2u(__floats2half2_rn(v10.x, v10.y));
        za[2] = h2u(__floats2half2_rn(v01.x, v01.y));
        za[3] = h2u(__floats2half2_rn(v11.x, v11.y));
    }

    // stage first chunk of this segment into buf 0
    {
        int fb = c0 * NC;
#pragma unroll
        for (int i = 0; i < 4; i++) {
            int idx = tid + i * 256;
            int r = idx >> 6, f = idx & 63;
            sb1[0][f][r] = __float2half_rn(b1g[(size_t)r * FFD + fb + f]);
        }
#pragma unroll
        for (int i = 0; i < 2; i++) {
            int idx = tid + i * 256;
            int r = idx >> 5, f2 = idx & 31;
            float2 v = *(const float2*)&a2g[(size_t)r * FFD + fb + f2 * 2];
            *(__half2*)&sa2[0][r][f2 * 2] = __floats2half2_rn(v.x, v.y);
        }
    }
    __syncthreads();

    float zacc[2][4];
#pragma unroll
    for (int j = 0; j < 2; j++)
#pragma unroll
        for (int q = 0; q < 4; q++) zacc[j][q] = 0.f;

    for (int ci = 0; ci < NCHUNK_SEG; ci++) {
        int cur = ci & 1, nxt = cur ^ 1;
        bool have_next = (ci + 1 < NCHUNK_SEG);

        // prefetch next chunk into regs
        float pb[4];
        float2 pa[2];
        if (have_next) {
            int fb = (c0 + ci + 1) * NC;
#pragma unroll
            for (int i = 0; i < 4; i++) {
                int idx = tid + i * 256;
                pb[i] = b1g[(size_t)(idx >> 6) * FFD + fb + (idx & 63)];
            }
#pragma unroll
            for (int i = 0; i < 2; i++) {
                int idx = tid + i * 256;
                pa[i] = *(const float2*)&a2g[(size_t)(idx >> 5) * FFD + fb + (idx & 31) * 2];
            }
        }

        // GEMM1: hpre[16 tok, 64 f] = z1 @ B1chunk
        float c1[8][4];
#pragma unroll
        for (int j = 0; j < 8; j++) {
            uint32_t bf[2];
            bf[0] = *(const uint32_t*)&sb1[cur][8 * j + (lane >> 2)][kcol];
            bf[1] = *(const uint32_t*)&sb1[cur][8 * j + (lane >> 2)][kcol + 8];
            float zero4[4] = {0.f, 0.f, 0.f, 0.f};
            mma16816(c1[j], za, bf, zero4);
        }

        // G elementwise + pack C-frags into A-frags for GEMM2
        uint32_t ga[4][4];
        float tmax = 0.f;
#pragma unroll
        for (int j = 0; j < 8; j++) {
#pragma unroll
            for (int q = 0; q < 2; q++) {
                float x0 = c1[j][2 * q], x1 = c1[j][2 * q + 1];
                u64 xv = pack2(x0, x1);
                u64 tv = ffma2(xv, xv, 0ull);
                u64 qv = ffma2(pack2(GC4, GC4), tv, pack2(GC3, GC3));
                qv = ffma2(qv, tv, pack2(GC2, GC2));
                qv = ffma2(qv, tv, pack2(GC1, GC1));
                qv = ffma2(qv, tv, pack2(GC0, GC0));
                u64 gv = ffma2(tv, qv, 0ull);
                float2 tf = unpack2(tv);
                tmax = fmaxf(tmax, fmaxf(tf.x, tf.y));
                float2 gf = unpack2(gv);
                ga[j >> 1][(j & 1) * 2 + q] = h2u(__floats2half2_rn(gf.x, gf.y));
            }
        }
        if (tmax > 1.0f) {             // |x|>1: exact fallback (data |x|<~0.6)
#pragma unroll
            for (int j = 0; j < 8; j++) {
#pragma unroll
                for (int q = 0; q < 2; q++) {
                    float x0 = c1[j][2 * q], x1 = c1[j][2 * q + 1];
                    float g0 = gelu_f(x0) - 0.5f * x0;
                    float g1 = gelu_f(x1) - 0.5f * x1;
                    ga[j >> 1][(j & 1) * 2 + q] = h2u(__floats2half2_rn(g0, g1));
                }
            }
        }

        // GEMM2: zacc += G @ A2chunk^T
#pragma unroll
        for (int j = 0; j < 2; j++) {
#pragma unroll
            for (int s = 0; s < 4; s++) {
                uint32_t bf[2];
                bf[0] = *(const uint32_t*)&sa2[cur][8 * j + (lane >> 2)][16 * s + kcol];
                bf[1] = *(const uint32_t*)&sa2[cur][8 * j + (lane >> 2)][16 * s + kcol + 8];
                mma16816(zacc[j], ga[s], bf, zacc[j]);
            }
        }

        // commit prefetched regs into the other buffer
        if (have_next) {
#pragma unroll
            for (int i = 0; i < 4; i++) {
                int idx = tid + i * 256;
                sb1[nxt][idx & 63][idx >> 6] = __float2half_rn(pb[i]);
            }
#pragma unroll
            for (int i = 0; i < 2; i++) {
                int idx = tid + i * 256;
                *(__half2*)&sa2[nxt][idx >> 5][(idx & 31) * 2] =
                    __floats2half2_rn(pa[i].x, pa[i].y);
            }
        }
        __syncthreads();
    }

    // epilogue: z2p[seg] = zacc (+ z1 @ M_e on seg 0)
    {
        int t0 = tok0 + mrow, t1 = t0 + 8;
#pragma unroll
        for (int j = 0; j < 2; j++) {
            u64 accq[2];
#pragma unroll
            for (int q = 0; q < 2; q++) {
                u64 acc = pack2(zacc[j][q], zacc[j][q + 2]);   // (row0, row1)
                accq[q] = acc;
            }
            if (seg == 0) {
                float z1a[RR], z1b[RR];
#pragma unroll
                for (int i = 0; i < 4; i++) {
                    float4 v = *(const float4*)&g_z1[(size_t)t0 * RR + i * 4];
                    float4 w = *(const float4*)&g_z1[(size_t)t1 * RR + i * 4];
                    z1a[i * 4 + 0] = v.x; z1a[i * 4 + 1] = v.y;
                    z1a[i * 4 + 2] = v.z; z1a[i * 4 + 3] = v.w;
                    z1b[i * 4 + 0] = w.x; z1b[i * 4 + 1] = w.y;
                    z1b[i * 4 + 2] = w.z; z1b[i * 4 + 3] = w.w;
                }
#pragma unroll
                for (int q = 0; q < 2; q++) {
                    int r2 = 8 * j + kcol + q;
                    u64 acc = accq[q];
#pragma unroll
                    for (int r1 = 0; r1 < RR; r1++) {
                        float m = sM[r1 * RR + r2];
                        acc = ffma2(pack2(z1a[r1], z1b[r1]), pack2(m, m), acc);
                    }
                    accq[q] = acc;
                }
            }
            float2 a0 = unpack2(accq[0]), a1 = unpack2(accq[1]);
            *(float2*)&z2o[(size_t)t0 * RR + 8 * j + kcol] = make_float2(a0.x, a1.x);
            *(float2*)&z2o[(size_t)t1 * RR + 8 * j + kcol] = make_float2(a0.y, a1.y);
        }
    }
}

// ---------------- k3: out = (z2p0 + z2p1) @ B2 ---------------------------------
__global__ __launch_bounds__(256) void k3_out(const float* __restrict__ w2B,
                                              float* __restrict__ out) {
    int tok0 = blockIdx.x * 32;
    int c4   = blockIdx.y * 256 + threadIdx.x;
    __shared__ float zs[32 * RR];
    __shared__ int se[32];
    for (int i = threadIdx.x; i < 32 * RR; i += 256)
        zs[i] = g_z2p[(size_t)tok0 * RR + i] +
                g_z2p[(size_t)TT * RR + (size_t)tok0 * RR + i];
    if (threadIdx.x < 32) se[threadIdx.x] = expert_of(tok0 + threadIdx.x);
    __syncthreads();

    int ecur = -1;
    u64 bp[RR * 2];
#pragma unroll 1
    for (int t = 0; t < 32; t++) {
        int e = se[t];
        if (e != ecur) {
            ecur = e;
            int ee = (e < EE) ? e : 0;
#pragma unroll
            for (int r = 0; r < RR; r++) {
                float4 b = *(const float4*)&w2B[(size_t)(ee * RR + r) * HH + c4 * 4];
                bp[r * 2]     = pack2(b.x, b.y);
                bp[r * 2 + 1] = pack2(b.z, b.w);
            }
        }
        u64 accA = 0ull, accB = 0ull;
#pragma unroll
        for (int r = 0; r < RR; r++) {
            float zv = zs[t * RR + r];
            u64 z2v = pack2(zv, zv);
            accA = ffma2(z2v, bp[r * 2], accA);
            accB = ffma2(z2v, bp[r * 2 + 1], accB);
        }
        float2 ra = unpack2(accA), rb = unpack2(accB);
        float4 o = make_float4(ra.x, ra.y, rb.x, rb.y);
        *(float4*)&out[(size_t)(tok0 + t) * HH + c4 * 4] = o;
    }
}

// ---------------- launch --------------------------------------------------------
extern "C" void kernel_launch(void* const* d_in, const int* in_sizes, int n_in,
                              void* d_out, int out_size) {
    const float* x   = (const float*)d_in[0];
    const void*  tpe = (const void*)d_in[1];
    const float* w1A = (const float*)d_in[2];
    const float* w1B = (const float*)d_in[3];
    const float* w2A = (const float*)d_in[4];
    const float* w2B = (const float*)d_in[5];
    float* out = (float*)d_out;

    k0_bounds<<<1, 32>>>(tpe);

    k_lin<<<EE * RR, 256>>>(w1B, w2A);

    k1_z1<<<TT / K1_TOK, 256>>>(x, w1A);

    dim3 g2(TT / MT, NSEG);
    k2_mma<<<g2, 256>>>(w1B, w2A);

    dim3 g3(TT / 32, HH / 1024);
    k3_out<<<g3, 256>>>(w2B, out);
}

// round 9
// speedup vs baseline: 4.5839x; 1.3113x over previous
#include <cuda_runtime.h>
#include <cuda_fp16.h>
#include <cstdint>

#define TT 16384
#define HH 2048
#define FFD 8192
#define EE 8
#define RR 16

#define NC 64                    // f-chunk width
#define NSEG 4                   // FF segments (CTA-parallel)
#define NCHUNK_TOT (FFD / NC)            // 128
#define NCHUNK_SEG (NCHUNK_TOT / NSEG)   // 32
#define MT 128                   // token tile per CTA

#define K1_TOK 64
#define K1_KC  64
#define K1_PADX 4

typedef unsigned long long u64;

// ---------------- scratch ------------------------------------------------------
__device__ float g_z1[TT * RR];                 // 1 MB
__device__ float g_z2p[NSEG * TT * RR];         // 4 MB (per-FF-segment partials)
__device__ float g_M[EE * RR * RR];             // per-expert 0.5*B1@A2^T
__device__ long long g_off[EE + 1];
// fp16 pre-swizzled weights (fragment-native layout), 2 MB each
__device__ __half g_cb1[EE * NCHUNK_TOT * 1024];
__device__ __half g_ca2[EE * NCHUNK_TOT * 1024];

// ---------------- scalar helpers ----------------------------------------------
__device__ __forceinline__ u64 ffma2(u64 a, u64 b, u64 c) {
    u64 d;
    asm("fma.rn.f32x2 %0, %1, %2, %3;" : "=l"(d) : "l"(a), "l"(b), "l"(c));
    return d;
}
__device__ __forceinline__ u64 pack2(float x, float y) {
    u64 r;
    asm("mov.b64 %0, {%1, %2};" : "=l"(r) : "f"(x), "f"(y));
    return r;
}
__device__ __forceinline__ float2 unpack2(u64 v) {
    float2 r;
    asm("mov.b64 {%0, %1}, %2;" : "=f"(r.x), "=f"(r.y) : "l"(v));
    return r;
}

// exact gelu (A&S 7.1.26 erf) — slow paths / rare fallback
__device__ __forceinline__ float gelu_f(float x) {
    float ax = fabsf(x) * 0.7071067811865475f;
    float t  = __fdividef(1.0f, fmaf(0.3275911f, ax, 1.0f));
    float p  = fmaf(t, 1.061405429f, -1.453152027f);
    p = fmaf(p, t, 1.421413741f);
    p = fmaf(p, t, -0.284496736f);
    p = fmaf(p, t, 0.254829592f);
    p *= t;
    float ex = __expf(-ax * ax);
    float er = fmaf(-p, ex, 1.0f);
    er = copysignf(er, x);
    return 0.5f * x * (1.0f + er);
}

// G(x) = gelu(x)-0.5x = t*Q(t), t=x^2; degree-2 Q valid t<=0.5 (err<=7.4e-5 at bound)
#define GC0 0.3989422804014327f
#define GC1 (-0.06649038006690545f)
#define GC2 0.009973557010035818f

__device__ __forceinline__ int expert_of(int t) {
    int e = 0;
#pragma unroll
    for (int i = 1; i <= EE; i++)
        if ((long long)t >= g_off[i]) e = i;
    return e;
}

// m16n8k16 fp16 MMA, fp32 accum (baseline PTX — legal on plain sm_103)
__device__ __forceinline__ void mma16816(float* d, const uint32_t* a,
                                         const uint32_t* b, const float* c) {
    asm volatile(
        "mma.sync.aligned.m16n8k16.row.col.f32.f16.f16.f32 "
        "{%0,%1,%2,%3}, {%4,%5,%6,%7}, {%8,%9}, {%10,%11,%12,%13};"
        : "=f"(d[0]), "=f"(d[1]), "=f"(d[2]), "=f"(d[3])
        : "r"(a[0]), "r"(a[1]), "r"(a[2]), "r"(a[3]),
          "r"(b[0]), "r"(b[1]),
          "f"(c[0]), "f"(c[1]), "f"(c[2]), "f"(c[3]));
}
__device__ __forceinline__ uint32_t h2u(__half2 h) { return *(uint32_t*)&h; }

// ---------------- k0: bounds (dtype-agnostic int32/int64) ----------------------
__global__ void k0_bounds(const void* __restrict__ tpe_raw) {
    if (threadIdx.x == 0) {
        const int* p32 = (const int*)tpe_raw;
        long long s32 = 0;
#pragma unroll
        for (int i = 0; i < EE; i++) s32 += (long long)p32[i];
        long long a = 0;
        g_off[0] = 0;
        if (s32 == (long long)TT) {
#pragma unroll
            for (int i = 0; i < EE; i++) { a += (long long)p32[i]; g_off[i + 1] = a; }
        } else {
            const long long* p64 = (const long long*)tpe_raw;
#pragma unroll
            for (int i = 0; i < EE; i++) { a += p64[i]; g_off[i + 1] = a; }
        }
    }
}

// ---------------- k_cvt: fp32 weights -> fp16 fragment-native tiles ------------
// cb1 chunk block (1024 halfs): [frow 0..63][group c 0..3][4 halfs r={2c,2c+1,2c+8,2c+9}]
// ca2 chunk block (1024 halfs): [tile j*4+s][nr 0..7][group c][4 halfs k=16s+{2c,2c+1,2c+8,2c+9}]
__global__ __launch_bounds__(256) void k_cvt(const float* __restrict__ w1B,
                                             const float* __restrict__ w2A) {
    __shared__ float tb[RR][NC];
    __shared__ float ta[RR][NC];
    int e = blockIdx.x >> 7;
    int chunk = blockIdx.x & 127;
    int tid = threadIdx.x;
#pragma unroll
    for (int i = 0; i < 4; i++) {
        int idx = tid + i * 256;
        int r = idx >> 6, f = idx & 63;
        tb[r][f] = w1B[(size_t)(e * RR + r) * FFD + chunk * NC + f];
        ta[r][f] = w2A[(size_t)(e * RR + r) * FFD + chunk * NC + f];
    }
    __syncthreads();
    size_t base = (size_t)(e * NCHUNK_TOT + chunk) * 1024;
    {
        // cb1: thread -> (frow = tid>>2, c = tid&3)
        int frow = tid >> 2, c = tid & 3;
        __half2 h0 = __floats2half2_rn(tb[2 * c][frow], tb[2 * c + 1][frow]);
        __half2 h1 = __floats2half2_rn(tb[2 * c + 8][frow], tb[2 * c + 9][frow]);
        uint2 v; v.x = h2u(h0); v.y = h2u(h1);
        *(uint2*)&g_cb1[base + frow * 16 + c * 4] = v;
    }
    {
        // ca2: thread -> (tile = tid>>5, nr = (tid>>2)&7, c = tid&3)
        int tile = tid >> 5, nr = (tid >> 2) & 7, c = tid & 3;
        int j = tile >> 2, s = tile & 3;
        int n = 8 * j + nr;
        __half2 h0 = __floats2half2_rn(ta[n][16 * s + 2 * c], ta[n][16 * s + 2 * c + 1]);
        __half2 h1 = __floats2half2_rn(ta[n][16 * s + 2 * c + 8], ta[n][16 * s + 2 * c + 9]);
        uint2 v; v.x = h2u(h0); v.y = h2u(h1);
        *(uint2*)&g_ca2[base + tile * 128 + nr * 16 + c * 4] = v;
    }
}

// ---------------- k_lin: g_M[e][r1][r2] = 0.5 * sum_f B1[r1][f]*A2[r2][f] ------
__global__ __launch_bounds__(256) void k_lin(const float* __restrict__ w1B,
                                             const float* __restrict__ w2A) {
    __shared__ float red[256 * RR];
    int e  = blockIdx.x >> 4;
    int r1 = blockIdx.x & 15;
    const float* b1 = w1B + (size_t)(e * RR + r1) * FFD;
    const float* a2 = w2A + (size_t)e * RR * FFD;
    float acc[RR];
#pragma unroll
    for (int r = 0; r < RR; r++) acc[r] = 0.f;
    for (int f = threadIdx.x; f < FFD; f += 256) {
        float bv = b1[f];
#pragma unroll
        for (int r2 = 0; r2 < RR; r2++)
            acc[r2] = fmaf(bv, a2[(size_t)r2 * FFD + f], acc[r2]);
    }
#pragma unroll
    for (int r = 0; r < RR; r++) red[threadIdx.x * RR + r] = acc[r];
    __syncthreads();
    for (int off = 128; off > 0; off >>= 1) {
        if (threadIdx.x < off) {
#pragma unroll
            for (int r = 0; r < RR; r++)
                red[threadIdx.x * RR + r] += red[(threadIdx.x + off) * RR + r];
        }
        __syncthreads();
    }
    if (threadIdx.x < RR)
        g_M[(e * RR + r1) * RR + threadIdx.x] = 0.5f * red[threadIdx.x];
}

// ---------------- k1: z1 = x @ A1^T — 64-token CTAs (256 blocks) ---------------
__global__ __launch_bounds__(128) void k1_z1(const float* __restrict__ x,
                                             const float* __restrict__ w1A) {
    __shared__ float xs[K1_TOK][K1_KC + K1_PADX];
    __shared__ float as_[RR][K1_KC];
    __shared__ float part[K1_TOK][RR];

    int tid  = threadIdx.x;
    int lt   = tid & 63;
    int half = tid >> 6;
    int tok0 = blockIdx.x * K1_TOK;
    int token = tok0 + lt;

    int e_first = expert_of(tok0);
    int e_last  = expert_of(tok0 + K1_TOK - 1);
    bool uni = (e_first == e_last);

    u64 acc2[RR];
#pragma unroll
    for (int r = 0; r < RR; r++) acc2[r] = 0ull;

    if (uni && e_first < EE) {
        const float* arow = w1A + (size_t)e_first * RR * HH;
        float4 px[8], pa[2];
#pragma unroll
        for (int j = 0; j < 8; j++) {
            int idx = tid + j * 128;            // 0..1023: 64 rows x 16 float4
            int row = idx >> 4, c4 = idx & 15;
            px[j] = *(const float4*)&x[(size_t)(tok0 + row) * HH + c4 * 4];
        }
#pragma unroll
        for (int j = 0; j < 2; j++) {
            int idx = tid + j * 128;            // 0..255: 16 rows x 16 float4
            int row = idx >> 4, c4 = idx & 15;
            pa[j] = *(const float4*)&arow[(size_t)row * HH + c4 * 4];
        }
        int kb = half * (K1_KC / 2);

        for (int c = 0; c < HH / K1_KC; c++) {
            __syncthreads();
#pragma unroll
            for (int j = 0; j < 8; j++) {
                int idx = tid + j * 128;
                int row = idx >> 4, c4 = idx & 15;
                *(float4*)&xs[row][c4 * 4] = px[j];
            }
#pragma unroll
            for (int j = 0; j < 2; j++) {
                int idx = tid + j * 128;
                int row = idx >> 4, c4 = idx & 15;
                *(float4*)&as_[row][c4 * 4] = pa[j];
            }
            __syncthreads();
            if (c + 1 < HH / K1_KC) {
                int kc = (c + 1) * K1_KC;
#pragma unroll
                for (int j = 0; j < 8; j++) {
                    int idx = tid + j * 128;
                    int row = idx >> 4, c4 = idx & 15;
                    px[j] = *(const float4*)&x[(size_t)(tok0 + row) * HH + kc + c4 * 4];
                }
#pragma unroll
                for (int j = 0; j < 2; j++) {
                    int idx = tid + j * 128;
                    int row = idx >> 4, c4 = idx & 15;
                    pa[j] = *(const float4*)&arow[(size_t)row * HH + kc + c4 * 4];
                }
            }
#pragma unroll 4
            for (int kp = 0; kp < 16; kp++) {
                int k = kb + kp * 2;
                u64 xv = *(const u64*)&xs[lt][k];
#pragma unroll
                for (int r = 0; r < RR; r++) {
                    u64 av = *(const u64*)&as_[r][k];
                    acc2[r] = ffma2(xv, av, acc2[r]);
                }
            }
        }
    } else {
        int e = expert_of(token);
        if (e < EE) {
            const float* xrow = x + (size_t)token * HH;
            const float* arow = w1A + (size_t)e * RR * HH;
            for (int k = half * 1024; k < half * 1024 + 1024; k += 2) {
                u64 xv = pack2(xrow[k], xrow[k + 1]);
#pragma unroll
                for (int r = 0; r < RR; r++) {
                    u64 av = pack2(__ldg(&arow[(size_t)r * HH + k]),
                                   __ldg(&arow[(size_t)r * HH + k + 1]));
                    acc2[r] = ffma2(xv, av, acc2[r]);
                }
            }
        }
    }

    __syncthreads();
    if (half == 1) {
#pragma unroll
        for (int r = 0; r < RR; r++) {
            float2 v = unpack2(acc2[r]);
            part[lt][r] = v.x + v.y;
        }
    }
    __syncthreads();
    if (half == 0) {
#pragma unroll
        for (int i = 0; i < 4; i++) {
            float4 o;
            float2 v0 = unpack2(acc2[i * 4 + 0]);
            float2 v1 = unpack2(acc2[i * 4 + 1]);
            float2 v2 = unpack2(acc2[i * 4 + 2]);
            float2 v3 = unpack2(acc2[i * 4 + 3]);
            o.x = v0.x + v0.y + part[lt][i * 4 + 0];
            o.y = v1.x + v1.y + part[lt][i * 4 + 1];
            o.z = v2.x + v2.y + part[lt][i * 4 + 2];
            o.w = v3.x + v3.y + part[lt][i * 4 + 3];
            *(float4*)&g_z1[token * RR + i * 4] = o;
        }
    }
}

// ---------------- k2: fused middle via warp MMA, pre-swizzled fp16 weights -----
// z2p[seg] = (seg==0 ? z1 @ M_e : 0) + G(z1 @ B1seg) @ A2seg^T
__global__ __launch_bounds__(256) void k2_mma(const float* __restrict__ w1B,
                                              const float* __restrict__ w2A) {
    __shared__ uint4 sb[2][128];    // 2KB per buffer: cb1 chunk block
    __shared__ uint4 sa[2][128];    // 2KB per buffer: ca2 chunk block
    __shared__ float sM[RR * RR];

    int tid  = threadIdx.x;
    int warp = tid >> 5, lane = tid & 31;
    int tok0 = blockIdx.x * MT;
    int seg  = blockIdx.y;
    int c0   = seg * NCHUNK_SEG;
    float* z2o = g_z2p + (size_t)seg * TT * RR;

    int e_first = expert_of(tok0);
    int e_last  = expert_of(tok0 + MT - 1);
    bool uni = (e_first == e_last);

    if (!uni) {
        // slow path: exact fp32 per token over this segment's f range
        if (tid < MT) {
            int token = tok0 + tid;
            int e = expert_of(token);
            float acc[RR];
#pragma unroll
            for (int r = 0; r < RR; r++) acc[r] = 0.f;
            if (e < EE) {
                float zr[RR];
#pragma unroll
                for (int r = 0; r < RR; r++) zr[r] = g_z1[token * RR + r];
                const float* b1 = w1B + (size_t)e * RR * FFD;
                const float* a2 = w2A + (size_t)e * RR * FFD;
                int f0 = c0 * NC, f1 = f0 + NCHUNK_SEG * NC;
                for (int f = f0; f < f1; f++) {
                    float hv = 0.f;
#pragma unroll
                    for (int r = 0; r < RR; r++)
                        hv = fmaf(zr[r], b1[(size_t)r * FFD + f], hv);
                    float h = gelu_f(hv);
#pragma unroll
                    for (int r = 0; r < RR; r++)
                        acc[r] = fmaf(h, a2[(size_t)r * FFD + f], acc[r]);
                }
            }
#pragma unroll
            for (int r = 0; r < RR; r++) z2o[token * RR + r] = acc[r];
        }
        return;
    }
    if (e_first >= EE) {
        if (tid < MT) {
#pragma unroll
            for (int i = 0; i < 4; i++)
                *(float4*)&z2o[(size_t)(tok0 + tid) * RR + i * 4] =
                    make_float4(0.f, 0.f, 0.f, 0.f);
        }
        return;
    }

    // ---- fast path ----
    int e = e_first;
    const uint4* cb = (const uint4*)&g_cb1[(size_t)(e * NCHUNK_TOT + c0) * 1024];
    const uint4* ca = (const uint4*)&g_ca2[(size_t)(e * NCHUNK_TOT + c0) * 1024];
    // each chunk block = 128 uint4

    sM[tid] = g_M[e * 256 + tid];

    // z1 A-fragment (m16k16)
    int mrow = warp * 16 + (lane >> 2);
    int kcol = (lane & 3) * 2;
    uint32_t za[4];
    {
        float2 v00 = *(const float2*)&g_z1[(tok0 + mrow) * RR + kcol];
        float2 v10 = *(const float2*)&g_z1[(tok0 + mrow + 8) * RR + kcol];
        float2 v01 = *(const float2*)&g_z1[(tok0 + mrow) * RR + kcol + 8];
        float2 v11 = *(const float2*)&g_z1[(tok0 + mrow + 8) * RR + kcol + 8];
        za[0] = h2u(__floats2half2_rn(v00.x, v00.y));
        za[1] = h2u(__floats2half2_rn(v10.x, v10.y));
        za[2] = h2u(__floats2half2_rn(v01.x, v01.y));
        za[3] = h2u(__floats2half2_rn(v11.x, v11.y));
    }

    // stage chunk 0 into buf 0: 256 threads x 16B
    if (tid < 128) sb[0][tid] = cb[tid];
    else           sa[0][tid - 128] = ca[tid - 128];
    __syncthreads();

    float zacc[2][4];
#pragma unroll
    for (int j = 0; j < 2; j++)
#pragma unroll
        for (int q = 0; q < 4; q++) zacc[j][q] = 0.f;

    // per-lane fragment byte offset within a tile row group
    uint32_t foff = (uint32_t)(lane >> 2) * 32 + (uint32_t)(lane & 3) * 8;
    const u64 gc2p = pack2(GC2, GC2);
    const u64 gc1p = pack2(GC1, GC1);
    const u64 gc0p = pack2(GC0, GC0);

    for (int ci = 0; ci < NCHUNK_SEG; ci++) {
        int cur = ci & 1, nxt = cur ^ 1;
        bool have_next = (ci + 1 < NCHUNK_SEG);

        // prefetch next chunk block into regs (1 uint4 per thread)
        uint4 pf;
        if (have_next) {
            if (tid < 128) pf = cb[(ci + 1) * 128 + tid];
            else           pf = ca[(ci + 1) * 128 + tid - 128];
        }

        const char* sbp = (const char*)&sb[cur][0];
        const char* sap = (const char*)&sa[cur][0];

        // GEMM1: hpre[16 tok, 64 f] = z1 @ B1chunk  (1 LDS.64 per j)
        float c1[8][4];
#pragma unroll
        for (int j = 0; j < 8; j++) {
            uint2 bf = *(const uint2*)(sbp + j * 256 + foff);
            float zero4[4] = {0.f, 0.f, 0.f, 0.f};
            mma16816(c1[j], za, (const uint32_t*)&bf, zero4);
        }

        // G elementwise (degree-2, f32x2) + pack into A-frags
        uint32_t ga[4][4];
        float tmax = 0.f;
#pragma unroll
        for (int j = 0; j < 8; j++) {
#pragma unroll
            for (int q = 0; q < 2; q++) {
                float x0 = c1[j][2 * q], x1 = c1[j][2 * q + 1];
                u64 xv = pack2(x0, x1);
                u64 tv = ffma2(xv, xv, 0ull);
                u64 qv = ffma2(gc2p, tv, gc1p);
                qv = ffma2(qv, tv, gc0p);
                u64 gv = ffma2(tv, qv, 0ull);
                float2 tf = unpack2(tv);
                tmax = fmaxf(tmax, fmaxf(tf.x, tf.y));
                float2 gf = unpack2(gv);
                ga[j >> 1][(j & 1) * 2 + q] = h2u(__floats2half2_rn(gf.x, gf.y));
            }
        }
        if (tmax > 0.5f) {             // |x|>0.707: exact fallback (never in-dist)
#pragma unroll
            for (int j = 0; j < 8; j++) {
#pragma unroll
                for (int q = 0; q < 2; q++) {
                    float x0 = c1[j][2 * q], x1 = c1[j][2 * q + 1];
                    float g0 = gelu_f(x0) - 0.5f * x0;
                    float g1 = gelu_f(x1) - 0.5f * x1;
                    ga[j >> 1][(j & 1) * 2 + q] = h2u(__floats2half2_rn(g0, g1));
                }
            }
        }

        // GEMM2: zacc += G @ A2chunk^T  (1 LDS.64 per (j,s))
#pragma unroll
        for (int j = 0; j < 2; j++) {
#pragma unroll
            for (int s = 0; s < 4; s++) {
                uint2 bf = *(const uint2*)(sap + (j * 4 + s) * 256 + foff);
                mma16816(zacc[j], ga[s], (const uint32_t*)&bf, zacc[j]);
            }
        }

        // commit prefetched block into the other buffer
        if (have_next) {
            if (tid < 128) sb[nxt][tid] = pf;
            else           sa[nxt][tid - 128] = pf;
        }
        __syncthreads();
    }

    // epilogue: z2p[seg] = zacc (+ z1 @ M_e on seg 0)
    {
        int t0 = tok0 + mrow, t1 = t0 + 8;
#pragma unroll
        for (int j = 0; j < 2; j++) {
            u64 accq[2];
#pragma unroll
            for (int q = 0; q < 2; q++)
                accq[q] = pack2(zacc[j][q], zacc[j][q + 2]);   // (row0, row1)
            if (seg == 0) {
                float z1a[RR], z1b[RR];
#pragma unroll
                for (int i = 0; i < 4; i++) {
                    float4 v = *(const float4*)&g_z1[(size_t)t0 * RR + i * 4];
                    float4 w = *(const float4*)&g_z1[(size_t)t1 * RR + i * 4];
                    z1a[i * 4 + 0] = v.x; z1a[i * 4 + 1] = v.y;
                    z1a[i * 4 + 2] = v.z; z1a[i * 4 + 3] = v.w;
                    z1b[i * 4 + 0] = w.x; z1b[i * 4 + 1] = w.y;
                    z1b[i * 4 + 2] = w.z; z1b[i * 4 + 3] = w.w;
                }
#pragma unroll
                for (int q = 0; q < 2; q++) {
                    int r2 = 8 * j + kcol + q;
                    u64 acc = accq[q];
#pragma unroll
                    for (int r1 = 0; r1 < RR; r1++) {
                        float m = sM[r1 * RR + r2];
                        acc = ffma2(pack2(z1a[r1], z1b[r1]), pack2(m, m), acc);
                    }
                    accq[q] = acc;
                }
            }
            float2 a0 = unpack2(accq[0]), a1 = unpack2(accq[1]);
            *(float2*)&z2o[(size_t)t0 * RR + 8 * j + kcol] = make_float2(a0.x, a1.x);
            *(float2*)&z2o[(size_t)t1 * RR + 8 * j + kcol] = make_float2(a0.y, a1.y);
        }
    }
}

// ---------------- k3: out = (sum_seg z2p) @ B2 ---------------------------------
__global__ __launch_bounds__(256) void k3_out(const float* __restrict__ w2B,
                                              float* __restrict__ out) {
    int tok0 = blockIdx.x * 32;
    int c4   = blockIdx.y * 256 + threadIdx.x;
    __shared__ float zs[32 * RR];
    __shared__ int se[32];
    for (int i = threadIdx.x; i < 32 * RR; i += 256) {
        float s = 0.f;
#pragma unroll
        for (int g = 0; g < NSEG; g++)
            s += g_z2p[(size_t)g * TT * RR + (size_t)tok0 * RR + i];
        zs[i] = s;
    }
    if (threadIdx.x < 32) se[threadIdx.x] = expert_of(tok0 + threadIdx.x);
    __syncthreads();

    int ecur = -1;
    u64 bp[RR * 2];
#pragma unroll 1
    for (int t = 0; t < 32; t++) {
        int e = se[t];
        if (e != ecur) {
            ecur = e;
            int ee = (e < EE) ? e : 0;
#pragma unroll
            for (int r = 0; r < RR; r++) {
                float4 b = *(const float4*)&w2B[(size_t)(ee * RR + r) * HH + c4 * 4];
                bp[r * 2]     = pack2(b.x, b.y);
                bp[r * 2 + 1] = pack2(b.z, b.w);
            }
        }
        u64 accA = 0ull, accB = 0ull;
#pragma unroll
        for (int r = 0; r < RR; r++) {
            float zv = zs[t * RR + r];
            u64 z2v = pack2(zv, zv);
            accA = ffma2(z2v, bp[r * 2], accA);
            accB = ffma2(z2v, bp[r * 2 + 1], accB);
        }
        float2 ra = unpack2(accA), rb = unpack2(accB);
        float4 o = make_float4(ra.x, ra.y, rb.x, rb.y);
        *(float4*)&out[(size_t)(tok0 + t) * HH + c4 * 4] = o;
    }
}

// ---------------- launch --------------------------------------------------------
extern "C" void kernel_launch(void* const* d_in, const int* in_sizes, int n_in,
                              void* d_out, int out_size) {
    const float* x   = (const float*)d_in[0];
    const void*  tpe = (const void*)d_in[1];
    const float* w1A = (const float*)d_in[2];
    const float* w1B = (const float*)d_in[3];
    const float* w2A = (const float*)d_in[4];
    const float* w2B = (const float*)d_in[5];
    float* out = (float*)d_out;

    k0_bounds<<<1, 32>>>(tpe);

    k_cvt<<<EE * NCHUNK_TOT, 256>>>(w1B, w2A);

    k_lin<<<EE * RR, 256>>>(w1B, w2A);

    k1_z1<<<TT / K1_TOK, 128>>>(x, w1A);

    dim3 g2(TT / MT, NSEG);
    k2_mma<<<g2, 256>>>(w1B, w2A);

    dim3 g3(TT / 32, HH / 1024);
    k3_out<<<g3, 256>>>(w2B, out);
}